// round 10
// baseline (speedup 1.0000x reference)
#include <cuda_runtime.h>
#include <cuda_fp16.h>
#include <cstdint>

// ---------------- scratch (__device__ globals; no allocs allowed) -----------
__device__ __half g_aq[8192*1024];             // fp16 A inputs (single)
__device__ __half g_ak[8192*1024];
__device__ __half g_av[8192*1024];
__device__ __half g_ao1[8192*1024];            // attention out (single fp16)
__device__ __half g_wq1[1024*1024];            // weights single fp16
__device__ __half g_wk1[1024*1024];
__device__ __half g_wv1[1024*1024];
__device__ __half g_wo1[1024*1024];
__device__ __half g_qhi[4*16*2048*64];         // Q split (pre-scaled 0.125*log2e)
__device__ __half g_qlo[4*16*2048*64];
__device__ __half g_k1 [4*16*2048*64];         // K single
__device__ __half g_v1 [4*16*2048*64];         // V single
__device__ uint32_t g_mbits[4*2048*64];        // bit mask: 64 words per row

// ---------------- PTX helpers (generic ISA, valid at compute_103) -----------
__device__ __forceinline__ uint32_t smem_u32(const void* p) {
    uint32_t a;
    asm("{ .reg .u64 t; cvta.to.shared.u64 t, %1; cvt.u32.u64 %0, t; }"
        : "=r"(a) : "l"(p));
    return a;
}
__device__ __forceinline__ void cpa16(uint32_t dst, const void* src) {
    asm volatile("cp.async.cg.shared.global [%0], [%1], 16;"
                 :: "r"(dst), "l"(src) : "memory");
}
#define CP_COMMIT() asm volatile("cp.async.commit_group;" ::: "memory")
#define CP_WAIT(n)  asm volatile("cp.async.wait_group %0;" :: "n"(n) : "memory")

#define LDSM4(r0, r1, r2, r3, addr)                                          \
    asm volatile("ldmatrix.sync.aligned.m8n8.x4.shared.b16 {%0,%1,%2,%3}, [%4];" \
                 : "=r"(r0), "=r"(r1), "=r"(r2), "=r"(r3) : "r"(addr))
#define LDSM4T(r0, r1, r2, r3, addr)                                         \
    asm volatile("ldmatrix.sync.aligned.m8n8.x4.trans.shared.b16 {%0,%1,%2,%3}, [%4];" \
                 : "=r"(r0), "=r"(r1), "=r"(r2), "=r"(r3) : "r"(addr))

#define MMA16816(d, a, b)                                                    \
    asm volatile("mma.sync.aligned.m16n8k16.row.col.f32.f16.f16.f32 "        \
                 "{%0,%1,%2,%3}, {%4,%5,%6,%7}, {%8,%9}, {%0,%1,%2,%3};"     \
                 : "+f"((d)[0]), "+f"((d)[1]), "+f"((d)[2]), "+f"((d)[3])    \
                 : "r"((a)[0]), "r"((a)[1]), "r"((a)[2]), "r"((a)[3]),       \
                   "r"((b)[0]), "r"((b)[1]))

__device__ __forceinline__ uint32_t pack_h2(float a, float b) {
    __half2 h = __floats2half2_rn(a, b);
    return *reinterpret_cast<uint32_t*>(&h);
}
__device__ __forceinline__ float ex2f(float x) {
    float r;
    asm("ex2.approx.f32 %0, %1;" : "=f"(r) : "f"(x));
    return r;
}

// ---------------- conversions (fused launches) -------------------------------
__global__ __launch_bounds__(256) void conv_h1x3(
    const float4* __restrict__ s0, const float4* __restrict__ s1,
    const float4* __restrict__ s2, uint2* __restrict__ d0,
    uint2* __restrict__ d1, uint2* __restrict__ d2)
{
    int z = blockIdx.y;
    const float4* src = (z == 0) ? s0 : (z == 1) ? s1 : s2;
    uint2* dst = (z == 0) ? d0 : (z == 1) ? d1 : d2;
    int i = blockIdx.x * blockDim.x + threadIdx.x;
    float4 v = src[i];
    dst[i] = make_uint2(pack_h2(v.x, v.y), pack_h2(v.z, v.w));
}

__global__ __launch_bounds__(256) void conv_h1x4(
    const float4* __restrict__ s0, const float4* __restrict__ s1,
    const float4* __restrict__ s2, const float4* __restrict__ s3,
    uint2* __restrict__ d0, uint2* __restrict__ d1,
    uint2* __restrict__ d2, uint2* __restrict__ d3)
{
    int z = blockIdx.y;
    const float4* src = (z == 0) ? s0 : (z == 1) ? s1 : (z == 2) ? s2 : s3;
    uint2* dst = (z == 0) ? d0 : (z == 1) ? d1 : (z == 2) ? d2 : d3;
    int i = blockIdx.x * blockDim.x + threadIdx.x;
    float4 v = src[i];
    dst[i] = make_uint2(pack_h2(v.x, v.y), pack_h2(v.z, v.w));
}

__global__ __launch_bounds__(256) void conv_maskbits(
    const int* __restrict__ src, uint32_t* __restrict__ dst)
{
    int gw = (blockIdx.x * blockDim.x + threadIdx.x) >> 5;
    int lane = threadIdx.x & 31;
    int v = src[(size_t)gw * 32 + lane];
    uint32_t b = __ballot_sync(0xffffffffu, v != 0);
    if (lane == 0) dst[gw] = b;
}

// ---------------- fp16 single-term GEMM core (mma.sync) ---------------------
// C = A(fp16) @ W(fp16)^T. CTA 128x128, BK=64, 3-stage cp.async, 2 CTAs/SM.
#define G_MAT 16384
#define G_STAGE (2 * G_MAT)                  // A, W = 32768
#define G_SMEM (3 * G_STAGE)                 // 98304

__device__ __forceinline__ void g_stage2(
    uint32_t sb, const __half* __restrict__ pA, const __half* __restrict__ pW,
    int kt, int tid)
{
    const __half* srcs[2] = {pA, pW};
    #pragma unroll
    for (int m = 0; m < 2; ++m) {
        uint32_t mb = sb + m * G_MAT;
        const __half* sp = srcs[m];
        #pragma unroll
        for (int i = 0; i < 8; ++i) {
            int seg = tid + (i << 7);
            int row = seg >> 3, cs = seg & 7;
            cpa16(mb + row * 128 + ((cs << 4) ^ ((row & 7) << 4)),
                  sp + (size_t)row * 1024 + (kt << 6) + (cs << 3));
        }
    }
    CP_COMMIT();
}

#define GEMM_BODY(pA, pW)                                                    \
    g_stage2(sb0,           (pA), (pW), 0, tid);                             \
    g_stage2(sb0 + G_STAGE, (pA), (pW), 1, tid);                             \
    uint32_t af[4][4], wf[8][2];                                             \
    for (int j = 0; j < 16; ++j) {                                           \
        if (j < 15) { CP_WAIT(1); } else { CP_WAIT(0); }                     \
        __syncthreads();                                                     \
        if (j + 2 < 16)                                                      \
            g_stage2(sb0 + ((j + 2) % 3) * G_STAGE, (pA), (pW), j + 2, tid); \
        const uint32_t sb = sb0 + (j % 3) * G_STAGE;                         \
        _Pragma("unroll")                                                    \
        for (int kk = 0; kk < 4; ++kk) {                                     \
            const int x_ = (kk << 5) + lxh;                                  \
            _Pragma("unroll")                                                \
            for (int mi = 0; mi < 4; ++mi) {                                 \
                int row = wm + (mi << 4) + lr;                               \
                uint32_t ad = sb + row * 128 + (x_ ^ ((row & 7) << 4));      \
                LDSM4(af[mi][0], af[mi][1], af[mi][2], af[mi][3], ad);       \
            }                                                                \
            _Pragma("unroll")                                                \
            for (int g = 0; g < 4; ++g) {                                    \
                int row = wn + (g << 4) + lr;                                \
                uint32_t wd = sb + G_MAT + row * 128 +                       \
                              (x_ ^ ((row & 7) << 4));                       \
                uint32_t r0, r1, r2, r3;                                     \
                LDSM4(r0, r1, r2, r3, wd);                                   \
                wf[2*g][0] = r0; wf[2*g][1] = r2;                            \
                wf[2*g+1][0] = r1; wf[2*g+1][1] = r3;                        \
            }                                                                \
            _Pragma("unroll")                                                \
            for (int mi = 0; mi < 4; ++mi)                                   \
                _Pragma("unroll")                                            \
                for (int ni = 0; ni < 8; ++ni)                               \
                    MMA16816(acc[mi][ni], af[mi], wf[ni]);                   \
        }                                                                    \
    }

__global__ __launch_bounds__(128, 2) void gemm_qkv(
    const float* __restrict__ bq, const float* __restrict__ bk,
    const float* __restrict__ bv)
{
    extern __shared__ __align__(128) char dynsm[];
    __shared__ float bias_s[128];

    const int tid  = threadIdx.x;
    const int wid  = tid >> 5;
    const int lane = tid & 31;
    const int m0 = blockIdx.y << 7;
    const int n0 = blockIdx.x << 7;
    const int z  = blockIdx.z;
    const int wm = (wid >> 1) << 6;     // 0 or 64
    const int wn = (wid & 1) << 6;      // 0 or 64
    const int lr = lane & 15;
    const int lxh = (lane >> 4) << 4;

    const __half* A = (z == 0) ? g_aq  : (z == 1) ? g_ak  : g_av;
    const __half* W = (z == 0) ? g_wq1 : (z == 1) ? g_wk1 : g_wv1;
    const float* bias = (z == 0) ? bq : (z == 1) ? bk : bv;

    bias_s[tid] = bias[n0 + tid];

    const uint32_t sb0 = smem_u32(dynsm);
    const __half* pA = A + (size_t)m0 * 1024;
    const __half* pW = W + (size_t)n0 * 1024;

    float acc[4][8][4] = {};
    GEMM_BODY(pA, pW)

    // epilogue: scatter [B,H,S,dk]; z=0 Q split (pre-scaled 0.125*log2e), z=1 K, z=2 V
    const int rbase = m0 + wm + (lane >> 2);
    const int cbase = n0 + wn + ((lane & 3) << 1);
    #pragma unroll
    for (int mi = 0; mi < 4; ++mi) {
        #pragma unroll
        for (int ni = 0; ni < 8; ++ni) {
            int col = cbase + (ni << 3);
            float b0 = bias_s[col - n0], b1 = bias_s[col - n0 + 1];
            #pragma unroll
            for (int half = 0; half < 2; ++half) {
                int row = rbase + (mi << 4) + (half << 3);
                float v0 = acc[mi][ni][half*2]   + b0;
                float v1 = acc[mi][ni][half*2+1] + b1;
                int h = col >> 6, d = col & 63;
                int bb = row >> 11, s = row & 2047;
                size_t idx = ((size_t)((bb << 4) + h) * 2048 + s) * 64 + d;
                if (z == 0) {
                    v0 *= 0.18033688f; v1 *= 0.18033688f;   // 0.125 * log2(e)
                    __half h0 = __float2half_rn(v0), h1 = __float2half_rn(v1);
                    uint32_t hi = (uint32_t)*reinterpret_cast<uint16_t*>(&h0) |
                                  ((uint32_t)*reinterpret_cast<uint16_t*>(&h1) << 16);
                    uint32_t lo = pack_h2(v0 - __half2float(h0),
                                          v1 - __half2float(h1));
                    *reinterpret_cast<uint32_t*>(&g_qhi[idx]) = hi;
                    *reinterpret_cast<uint32_t*>(&g_qlo[idx]) = lo;
                } else if (z == 1) {
                    *reinterpret_cast<uint32_t*>(&g_k1[idx]) = pack_h2(v0, v1);
                } else {
                    *reinterpret_cast<uint32_t*>(&g_v1[idx]) = pack_h2(v0, v1);
                }
            }
        }
    }
}

__global__ __launch_bounds__(128, 2) void gemm_out(
    const float* __restrict__ bo, float* __restrict__ outf)
{
    extern __shared__ __align__(128) char dynsm[];
    __shared__ float bias_s[128];

    const int tid  = threadIdx.x;
    const int wid  = tid >> 5;
    const int lane = tid & 31;
    const int m0 = blockIdx.y << 7;
    const int n0 = blockIdx.x << 7;
    const int wm = (wid >> 1) << 6;
    const int wn = (wid & 1) << 6;
    const int lr = lane & 15;
    const int lxh = (lane >> 4) << 4;

    bias_s[tid] = bo[n0 + tid];

    const uint32_t sb0 = smem_u32(dynsm);
    const __half* pA = g_ao1 + (size_t)m0 * 1024;
    const __half* pW = g_wo1 + (size_t)n0 * 1024;

    float acc[4][8][4] = {};
    GEMM_BODY(pA, pW)

    const int rbase = m0 + wm + (lane >> 2);
    const int cbase = n0 + wn + ((lane & 3) << 1);
    #pragma unroll
    for (int mi = 0; mi < 4; ++mi)
        #pragma unroll
        for (int ni = 0; ni < 8; ++ni) {
            int col = cbase + (ni << 3);
            float b0 = bias_s[col - n0], b1 = bias_s[col - n0 + 1];
            #pragma unroll
            for (int half = 0; half < 2; ++half) {
                int row = rbase + (mi << 4) + (half << 3);
                *reinterpret_cast<float2*>(&outf[(size_t)row * 1024 + col]) =
                    make_float2(acc[mi][ni][half*2] + b0,
                                acc[mi][ni][half*2+1] + b1);
            }
        }
}

// ---------------- tensor-core flash attention --------------------------------
// CTA = 128 q-rows, 128 threads (4 warps x 32 q-rows), 2 CTAs/SM, 3-stage.
// Each warp owns 2 m16-tiles: K/V smem fragments feed 2x MMAs (traffic /2).
// S = (Qh+Ql) x K (2-term, exp2 domain); fixed-max softmax with immediate
// exp+pack (P resident in fp16x2 regs); O += P x V (single term).
#define ATT_KV 16384
#define ATT_MB 2048
#define ATT_STAGE (2*ATT_KV + ATT_MB)            // K, V, maskbits = 34816
#define ATT_SMEM (3*ATT_STAGE)                   // 104448

__device__ __forceinline__ void att_stage(
    uint32_t sb, const __half* __restrict__ K, const __half* __restrict__ V,
    const uint32_t* __restrict__ Mb, int kt, int q0, int tid)
{
    #pragma unroll
    for (int i = 0; i < 8; ++i) {
        int seg = tid + (i << 7);
        int row = seg >> 3, cs = seg & 7;
        uint32_t so = row * 128 + ((cs << 4) ^ ((row & 7) << 4));
        size_t gofs = (size_t)((kt << 7) + row) * 64 + (cs << 3);
        cpa16(sb + so,          K + gofs);
        cpa16(sb + ATT_KV + so, V + gofs);
    }
    cpa16(sb + 2*ATT_KV + tid * 16,
          (const char*)(Mb + (size_t)(q0 + tid) * 64) + (kt << 4));
    CP_COMMIT();
}

__global__ __launch_bounds__(128, 2) void attn_tc()
{
    extern __shared__ __align__(128) char sm[];
    const int tid  = threadIdx.x;
    const int wid  = tid >> 5;
    const int lane = tid & 31;
    const int bh = blockIdx.y;
    const int b = bh >> 4, h = bh & 15;
    const int q0 = blockIdx.x << 7;          // 128 q-rows per CTA

    const uint32_t smb = smem_u32(sm);

    const size_t hofs = (size_t)bh * 2048 * 64;
    const __half* gqh = g_qhi + hofs + (size_t)q0 * 64;
    const __half* gql = g_qlo + hofs + (size_t)q0 * 64;
    const __half* gk  = g_k1 + hofs;
    const __half* gv  = g_v1 + hofs;
    const uint32_t* gmb = g_mbits + (size_t)b * 2048 * 64;

    // ---- stage Q (hi, lo: 128 rows each) through buffer 0/1 space ----
    #pragma unroll
    for (int i = 0; i < 8; ++i) {
        int seg = tid + (i << 7);
        int row = seg >> 3, cs = seg & 7;
        uint32_t so = row * 128 + ((cs << 4) ^ ((row & 7) << 4));
        size_t gofs = (size_t)row * 64 + (cs << 3);
        cpa16(smb + so,         gqh + gofs);
        cpa16(smb + 16384 + so, gql + gofs);
    }
    CP_COMMIT();
    CP_WAIT(0);
    __syncthreads();

    const int lr  = lane & 15;
    const int lxh = (lane >> 4) << 4;
    const int r   = lane >> 2;
    const int c2  = (lane & 3) << 1;

    uint32_t qh[2][4][4], ql[2][4][4];
    #pragma unroll
    for (int m = 0; m < 2; ++m) {
        int row = (wid << 5) + (m << 4) + lr;
        uint32_t rb = smb + row * 128;
        uint32_t sw = (row & 7) << 4;
        #pragma unroll
        for (int kk = 0; kk < 4; ++kk) {
            uint32_t ad = rb + (((kk << 5) + lxh) ^ sw);
            LDSM4(qh[m][kk][0], qh[m][kk][1], qh[m][kk][2], qh[m][kk][3], ad);
            LDSM4(ql[m][kk][0], ql[m][kk][1], ql[m][kk][2], ql[m][kk][3],
                  ad + 16384);
        }
    }
    __syncthreads();   // all warps done reading Q before stage overwrite

    att_stage(smb,             gk, gv, gmb, 0, q0, tid);
    att_stage(smb + ATT_STAGE, gk, gv, gmb, 1, q0, tid);

    float o[2][8][4] = {};
    float lsum[2][2] = {};
    const int mrow = (wid << 5) + r;         // mask row base (local)

    for (int kt = 0; kt < 16; ++kt) {
        if (kt < 15) { CP_WAIT(1); } else { CP_WAIT(0); }
        __syncthreads();
        if (kt + 2 < 16)
            att_stage(smb + ((kt + 2) % 3) * ATT_STAGE, gk, gv, gmb,
                      kt + 2, q0, tid);
        const uint32_t sb = smb + (kt % 3) * ATT_STAGE;
        const char* stp = sm + (kt % 3) * ATT_STAGE + 2*ATT_KV;

        uint32_t P[2][32];
        uint32_t mw[4];

        // ---- S = (Qh + Ql) x K, exp+pack per 16-col group ----
        #pragma unroll
        for (int g = 0; g < 8; ++g) {
            if ((g & 1) == 0) {
                int wo = (g >> 1) << 2;
                mw[0] = *reinterpret_cast<const uint32_t*>(stp + (mrow)      * 16 + wo);
                mw[1] = *reinterpret_cast<const uint32_t*>(stp + (mrow + 8)  * 16 + wo);
                mw[2] = *reinterpret_cast<const uint32_t*>(stp + (mrow + 16) * 16 + wo);
                mw[3] = *reinterpret_cast<const uint32_t*>(stp + (mrow + 24) * 16 + wo);
            }
            float sc[2][2][4];
            #pragma unroll
            for (int m = 0; m < 2; ++m)
                #pragma unroll
                for (int n = 0; n < 2; ++n)
                    #pragma unroll
                    for (int j = 0; j < 4; ++j) sc[m][n][j] = 0.f;

            int krow = (g << 4) + lr;
            uint32_t rb = sb + krow * 128;
            uint32_t sw = (krow & 7) << 4;
            #pragma unroll
            for (int kk = 0; kk < 4; ++kk) {
                uint32_t ad = rb + (((kk << 5) + lxh) ^ sw);
                uint32_t k0r, k1r, k2r, k3r;
                LDSM4(k0r, k1r, k2r, k3r, ad);
                uint32_t bE[2] = {k0r, k2r}, bO[2] = {k1r, k3r};
                #pragma unroll
                for (int m = 0; m < 2; ++m) {
                    MMA16816(sc[m][0], qh[m][kk], bE);
                    MMA16816(sc[m][1], qh[m][kk], bO);
                    MMA16816(sc[m][0], ql[m][kk], bE);
                    MMA16816(sc[m][1], ql[m][kk], bO);
                }
            }

            const int sh = ((g & 1) << 4) + c2;
            #pragma unroll
            for (int m = 0; m < 2; ++m) {
                uint32_t w0 = mw[m*2], w1 = mw[m*2+1];
                float e00 = ((w0 >> sh) & 1u)       ? ex2f(sc[m][0][0]) : 1.0f;
                float e01 = ((w0 >> (sh+1)) & 1u)   ? ex2f(sc[m][0][1]) : 1.0f;
                float e02 = ((w1 >> sh) & 1u)       ? ex2f(sc[m][0][2]) : 1.0f;
                float e03 = ((w1 >> (sh+1)) & 1u)   ? ex2f(sc[m][0][3]) : 1.0f;
                float e10 = ((w0 >> (sh+8)) & 1u)   ? ex2f(sc[m][1][0]) : 1.0f;
                float e11 = ((w0 >> (sh+9)) & 1u)   ? ex2f(sc[m][1][1]) : 1.0f;
                float e12 = ((w1 >> (sh+8)) & 1u)   ? ex2f(sc[m][1][2]) : 1.0f;
                float e13 = ((w1 >> (sh+9)) & 1u)   ? ex2f(sc[m][1][3]) : 1.0f;
                lsum[m][0] += (e00 + e01) + (e10 + e11);
                lsum[m][1] += (e02 + e03) + (e12 + e13);
                P[m][g*4+0] = pack_h2(e00, e01);
                P[m][g*4+1] = pack_h2(e02, e03);
                P[m][g*4+2] = pack_h2(e10, e11);
                P[m][g*4+3] = pack_h2(e12, e13);
            }
        }

        // ---- O += P x V (V fragments shared across both m-tiles) ----
        #pragma unroll
        for (int t = 0; t < 8; ++t) {
            int vrow = (t << 4) + lr;
            uint32_t rb = sb + ATT_KV + vrow * 128;
            uint32_t sw = (vrow & 7) << 4;
            #pragma unroll
            for (int dp = 0; dp < 4; ++dp) {
                uint32_t ad = rb + (((dp << 5) + lxh) ^ sw);
                uint32_t h0, h1, h2, h3;
                LDSM4T(h0, h1, h2, h3, ad);
                uint32_t bh0[2] = {h0, h1}, bh1[2] = {h2, h3};
                #pragma unroll
                for (int m = 0; m < 2; ++m) {
                    MMA16816(o[m][2*dp],   &P[m][t*4], bh0);
                    MMA16816(o[m][2*dp+1], &P[m][t*4], bh1);
                }
            }
        }
    }

    // ---- reduce l across quad, normalize, store [B,S,1024] fp16 ----
    #pragma unroll
    for (int m = 0; m < 2; ++m) {
        #pragma unroll
        for (int hh = 0; hh < 2; ++hh) {
            lsum[m][hh] += __shfl_xor_sync(~0u, lsum[m][hh], 1);
            lsum[m][hh] += __shfl_xor_sync(~0u, lsum[m][hh], 2);
        }
        float i0 = 1.f / lsum[m][0], i1 = 1.f / lsum[m][1];
        int row0 = q0 + (wid << 5) + (m << 4) + r;
        size_t base0 = ((size_t)(b * 2048) + row0) * 1024 + h * 64;
        size_t base1 = base0 + 8 * 1024;
        #pragma unroll
        for (int ni = 0; ni < 8; ++ni) {
            int d = (ni << 3) + c2;
            *reinterpret_cast<uint32_t*>(&g_ao1[base0 + d]) =
                pack_h2(o[m][ni][0] * i0, o[m][ni][1] * i0);
            *reinterpret_cast<uint32_t*>(&g_ao1[base1 + d]) =
                pack_h2(o[m][ni][2] * i1, o[m][ni][3] * i1);
        }
    }
}

// ---------------------------------------------------------------------------
extern "C" void kernel_launch(void* const* d_in, const int* in_sizes, int n_in,
                              void* d_out, int out_size)
{
    const float* query = (const float*)d_in[0];
    const float* key_  = (const float*)d_in[1];
    const float* value = (const float*)d_in[2];
    const int*   mask  = (const int*)  d_in[3];
    const float* wq = (const float*)d_in[4];
    const float* bq = (const float*)d_in[5];
    const float* wk = (const float*)d_in[6];
    const float* bk = (const float*)d_in[7];
    const float* wv = (const float*)d_in[8];
    const float* bv = (const float*)d_in[9];
    const float* wo = (const float*)d_in[10];
    const float* bo = (const float*)d_in[11];

    void *paq, *pak, *pav, *pwq, *pwk, *pwv, *pwo, *pmb;
    cudaGetSymbolAddress(&paq, g_aq);
    cudaGetSymbolAddress(&pak, g_ak);
    cudaGetSymbolAddress(&pav, g_av);
    cudaGetSymbolAddress(&pwq, g_wq1);
    cudaGetSymbolAddress(&pwk, g_wk1);
    cudaGetSymbolAddress(&pwv, g_wv1);
    cudaGetSymbolAddress(&pwo, g_wo1);
    cudaGetSymbolAddress(&pmb, g_mbits);

    cudaFuncSetAttribute(gemm_qkv,
                         cudaFuncAttributeMaxDynamicSharedMemorySize, G_SMEM);
    cudaFuncSetAttribute(gemm_out,
                         cudaFuncAttributeMaxDynamicSharedMemorySize, G_SMEM);
    cudaFuncSetAttribute(attn_tc,
                         cudaFuncAttributeMaxDynamicSharedMemorySize, ATT_SMEM);

    conv_maskbits<<<65536, 256>>>(mask, (uint32_t*)pmb);
    conv_h1x3<<<dim3(8192, 3), 256>>>(
        (const float4*)query, (const float4*)key_, (const float4*)value,
        (uint2*)paq, (uint2*)pak, (uint2*)pav);
    conv_h1x4<<<dim3(1024, 4), 256>>>(
        (const float4*)wq, (const float4*)wk, (const float4*)wv,
        (const float4*)wo,
        (uint2*)pwq, (uint2*)pwk, (uint2*)pwv, (uint2*)pwo);

    gemm_qkv<<<dim3(8, 64, 3), 128, G_SMEM>>>(bq, bk, bv);
    attn_tc<<<dim3(16, 64), 128, ATT_SMEM>>>();
    gemm_out<<<dim3(8, 64), 128, G_SMEM>>>(bo, (float*)d_out);
}

// round 11
// speedup vs baseline: 1.1218x; 1.1218x over previous
#include <cuda_runtime.h>
#include <cuda_fp16.h>
#include <cstdint>

// ---------------- scratch (__device__ globals; no allocs allowed) -----------
__device__ __half g_aq[8192*1024];             // fp16 A inputs (single)
__device__ __half g_ak[8192*1024];
__device__ __half g_av[8192*1024];
__device__ __half g_ao1[8192*1024];            // attention out (single fp16)
__device__ __half g_wq1[1024*1024];            // weights single fp16
__device__ __half g_wk1[1024*1024];
__device__ __half g_wv1[1024*1024];
__device__ __half g_wo1[1024*1024];
__device__ __half g_qhi[4*16*2048*64];         // Q split (pre-scaled 0.125*log2e)
__device__ __half g_qlo[4*16*2048*64];
__device__ __half g_k1 [4*16*2048*64];         // K single
__device__ __half g_v1 [4*16*2048*64];         // V single
__device__ uint32_t g_mbits[4*2048*64];        // bit mask: 64 words per row

// ---------------- PTX helpers (generic ISA, valid at compute_103) -----------
__device__ __forceinline__ uint32_t smem_u32(const void* p) {
    uint32_t a;
    asm("{ .reg .u64 t; cvta.to.shared.u64 t, %1; cvt.u32.u64 %0, t; }"
        : "=r"(a) : "l"(p));
    return a;
}
__device__ __forceinline__ void cpa16(uint32_t dst, const void* src) {
    asm volatile("cp.async.cg.shared.global [%0], [%1], 16;"
                 :: "r"(dst), "l"(src) : "memory");
}
#define CP_COMMIT() asm volatile("cp.async.commit_group;" ::: "memory")
#define CP_WAIT(n)  asm volatile("cp.async.wait_group %0;" :: "n"(n) : "memory")

#define LDSM4(r0, r1, r2, r3, addr)                                          \
    asm volatile("ldmatrix.sync.aligned.m8n8.x4.shared.b16 {%0,%1,%2,%3}, [%4];" \
                 : "=r"(r0), "=r"(r1), "=r"(r2), "=r"(r3) : "r"(addr))
#define LDSM4T(r0, r1, r2, r3, addr)                                         \
    asm volatile("ldmatrix.sync.aligned.m8n8.x4.trans.shared.b16 {%0,%1,%2,%3}, [%4];" \
                 : "=r"(r0), "=r"(r1), "=r"(r2), "=r"(r3) : "r"(addr))

#define MMA16816(d, a, b)                                                    \
    asm volatile("mma.sync.aligned.m16n8k16.row.col.f32.f16.f16.f32 "        \
                 "{%0,%1,%2,%3}, {%4,%5,%6,%7}, {%8,%9}, {%0,%1,%2,%3};"     \
                 : "+f"((d)[0]), "+f"((d)[1]), "+f"((d)[2]), "+f"((d)[3])    \
                 : "r"((a)[0]), "r"((a)[1]), "r"((a)[2]), "r"((a)[3]),       \
                   "r"((b)[0]), "r"((b)[1]))

__device__ __forceinline__ uint32_t pack_h2(float a, float b) {
    __half2 h = __floats2half2_rn(a, b);
    return *reinterpret_cast<uint32_t*>(&h);
}
__device__ __forceinline__ float ex2f(float x) {
    float r;
    asm("ex2.approx.f32 %0, %1;" : "=f"(r) : "f"(x));
    return r;
}

// ---------------- conversions (fused launches) -------------------------------
__global__ __launch_bounds__(256) void conv_h1x3(
    const float4* __restrict__ s0, const float4* __restrict__ s1,
    const float4* __restrict__ s2, uint2* __restrict__ d0,
    uint2* __restrict__ d1, uint2* __restrict__ d2)
{
    int z = blockIdx.y;
    const float4* src = (z == 0) ? s0 : (z == 1) ? s1 : s2;
    uint2* dst = (z == 0) ? d0 : (z == 1) ? d1 : d2;
    int i = blockIdx.x * blockDim.x + threadIdx.x;
    float4 v = src[i];
    dst[i] = make_uint2(pack_h2(v.x, v.y), pack_h2(v.z, v.w));
}

__global__ __launch_bounds__(256) void conv_h1x4(
    const float4* __restrict__ s0, const float4* __restrict__ s1,
    const float4* __restrict__ s2, const float4* __restrict__ s3,
    uint2* __restrict__ d0, uint2* __restrict__ d1,
    uint2* __restrict__ d2, uint2* __restrict__ d3)
{
    int z = blockIdx.y;
    const float4* src = (z == 0) ? s0 : (z == 1) ? s1 : (z == 2) ? s2 : s3;
    uint2* dst = (z == 0) ? d0 : (z == 1) ? d1 : (z == 2) ? d2 : d3;
    int i = blockIdx.x * blockDim.x + threadIdx.x;
    float4 v = src[i];
    dst[i] = make_uint2(pack_h2(v.x, v.y), pack_h2(v.z, v.w));
}

__global__ __launch_bounds__(256) void conv_maskbits(
    const int* __restrict__ src, uint32_t* __restrict__ dst)
{
    int gw = (blockIdx.x * blockDim.x + threadIdx.x) >> 5;
    int lane = threadIdx.x & 31;
    int v = src[(size_t)gw * 32 + lane];
    uint32_t b = __ballot_sync(0xffffffffu, v != 0);
    if (lane == 0) dst[gw] = b;
}

// ---------------- fp16 single-term GEMM core (mma.sync) ---------------------
// C = A(fp16) @ W(fp16)^T. CTA 128x128, BK=64, 3-stage cp.async, 2 CTAs/SM.
// 4 warps x 64x64 warptile, double-buffered ldmatrix fragments.
#define G_MAT 16384
#define G_STAGE (2 * G_MAT)                  // A, W = 32768
#define G_SMEM (3 * G_STAGE)                 // 98304

__device__ __forceinline__ void g_stage2(
    uint32_t sb, const __half* __restrict__ pA, const __half* __restrict__ pW,
    int kt, int tid)
{
    const __half* srcs[2] = {pA, pW};
    #pragma unroll
    for (int m = 0; m < 2; ++m) {
        uint32_t mb = sb + m * G_MAT;
        const __half* sp = srcs[m];
        #pragma unroll
        for (int i = 0; i < 8; ++i) {
            int seg = tid + (i << 7);
            int row = seg >> 3, cs = seg & 7;
            cpa16(mb + row * 128 + ((cs << 4) ^ ((row & 7) << 4)),
                  sp + (size_t)row * 1024 + (kt << 6) + (cs << 3));
        }
    }
    CP_COMMIT();
}

#define GLOAD(buf, kk, sb)                                                   \
    do {                                                                     \
        const int x_ = ((kk) << 5) + lxh;                                    \
        _Pragma("unroll")                                                    \
        for (int mi = 0; mi < 4; ++mi) {                                     \
            int row = wm + (mi << 4) + lr;                                   \
            uint32_t ad = (sb) + row * 128 + (x_ ^ ((row & 7) << 4));        \
            LDSM4(af[buf][mi][0], af[buf][mi][1], af[buf][mi][2],            \
                  af[buf][mi][3], ad);                                       \
        }                                                                    \
        _Pragma("unroll")                                                    \
        for (int g = 0; g < 4; ++g) {                                        \
            int row = wn + (g << 4) + lr;                                    \
            uint32_t wd = (sb) + G_MAT + row * 128 + (x_ ^ ((row & 7) << 4));\
            uint32_t r0, r1, r2, r3;                                         \
            LDSM4(r0, r1, r2, r3, wd);                                       \
            wf[buf][2*g][0] = r0; wf[buf][2*g][1] = r2;                      \
            wf[buf][2*g+1][0] = r1; wf[buf][2*g+1][1] = r3;                  \
        }                                                                    \
    } while (0)

#define GEMM_BODY(pA, pW)                                                    \
    g_stage2(sb0,           (pA), (pW), 0, tid);                             \
    g_stage2(sb0 + G_STAGE, (pA), (pW), 1, tid);                             \
    uint32_t af[2][4][4], wf[2][8][2];                                       \
    for (int j = 0; j < 16; ++j) {                                           \
        if (j < 15) { CP_WAIT(1); } else { CP_WAIT(0); }                     \
        __syncthreads();                                                     \
        if (j + 2 < 16)                                                      \
            g_stage2(sb0 + ((j + 2) % 3) * G_STAGE, (pA), (pW), j + 2, tid); \
        const uint32_t sb = sb0 + (j % 3) * G_STAGE;                         \
        GLOAD(0, 0, sb);                                                     \
        _Pragma("unroll")                                                    \
        for (int kk = 0; kk < 4; ++kk) {                                     \
            if (kk < 3) GLOAD((kk + 1) & 1, kk + 1, sb);                     \
            const int cb = kk & 1;                                           \
            _Pragma("unroll")                                                \
            for (int mi = 0; mi < 4; ++mi)                                   \
                _Pragma("unroll")                                            \
                for (int ni = 0; ni < 8; ++ni)                               \
                    MMA16816(acc[mi][ni], af[cb][mi], wf[cb][ni]);           \
        }                                                                    \
    }

__global__ __launch_bounds__(128, 2) void gemm_qkv(
    const float* __restrict__ bq, const float* __restrict__ bk,
    const float* __restrict__ bv)
{
    extern __shared__ __align__(128) char dynsm[];
    __shared__ float bias_s[128];

    const int tid  = threadIdx.x;
    const int wid  = tid >> 5;
    const int lane = tid & 31;
    const int m0 = blockIdx.y << 7;
    const int n0 = blockIdx.x << 7;
    const int z  = blockIdx.z;
    const int wm = (wid >> 1) << 6;     // 0 or 64
    const int wn = (wid & 1) << 6;      // 0 or 64
    const int lr = lane & 15;
    const int lxh = (lane >> 4) << 4;

    const __half* A = (z == 0) ? g_aq  : (z == 1) ? g_ak  : g_av;
    const __half* W = (z == 0) ? g_wq1 : (z == 1) ? g_wk1 : g_wv1;
    const float* bias = (z == 0) ? bq : (z == 1) ? bk : bv;

    bias_s[tid] = bias[n0 + tid];

    const uint32_t sb0 = smem_u32(dynsm);
    const __half* pA = A + (size_t)m0 * 1024;
    const __half* pW = W + (size_t)n0 * 1024;

    float acc[4][8][4] = {};
    GEMM_BODY(pA, pW)

    // epilogue: scatter [B,H,S,dk]; z=0 Q split (pre-scaled 0.125*log2e), z=1 K, z=2 V
    const int rbase = m0 + wm + (lane >> 2);
    const int cbase = n0 + wn + ((lane & 3) << 1);
    #pragma unroll
    for (int mi = 0; mi < 4; ++mi) {
        #pragma unroll
        for (int ni = 0; ni < 8; ++ni) {
            int col = cbase + (ni << 3);
            float b0 = bias_s[col - n0], b1 = bias_s[col - n0 + 1];
            #pragma unroll
            for (int half = 0; half < 2; ++half) {
                int row = rbase + (mi << 4) + (half << 3);
                float v0 = acc[mi][ni][half*2]   + b0;
                float v1 = acc[mi][ni][half*2+1] + b1;
                int h = col >> 6, d = col & 63;
                int bb = row >> 11, s = row & 2047;
                size_t idx = ((size_t)((bb << 4) + h) * 2048 + s) * 64 + d;
                if (z == 0) {
                    v0 *= 0.18033688f; v1 *= 0.18033688f;   // 0.125 * log2(e)
                    __half h0 = __float2half_rn(v0), h1 = __float2half_rn(v1);
                    uint32_t hi = (uint32_t)*reinterpret_cast<uint16_t*>(&h0) |
                                  ((uint32_t)*reinterpret_cast<uint16_t*>(&h1) << 16);
                    uint32_t lo = pack_h2(v0 - __half2float(h0),
                                          v1 - __half2float(h1));
                    *reinterpret_cast<uint32_t*>(&g_qhi[idx]) = hi;
                    *reinterpret_cast<uint32_t*>(&g_qlo[idx]) = lo;
                } else if (z == 1) {
                    *reinterpret_cast<uint32_t*>(&g_k1[idx]) = pack_h2(v0, v1);
                } else {
                    *reinterpret_cast<uint32_t*>(&g_v1[idx]) = pack_h2(v0, v1);
                }
            }
        }
    }
}

__global__ __launch_bounds__(128, 2) void gemm_out(
    const float* __restrict__ bo, float* __restrict__ outf)
{
    extern __shared__ __align__(128) char dynsm[];
    __shared__ float bias_s[128];

    const int tid  = threadIdx.x;
    const int wid  = tid >> 5;
    const int lane = tid & 31;
    const int m0 = blockIdx.y << 7;
    const int n0 = blockIdx.x << 7;
    const int wm = (wid >> 1) << 6;
    const int wn = (wid & 1) << 6;
    const int lr = lane & 15;
    const int lxh = (lane >> 4) << 4;

    bias_s[tid] = bo[n0 + tid];

    const uint32_t sb0 = smem_u32(dynsm);
    const __half* pA = g_ao1 + (size_t)m0 * 1024;
    const __half* pW = g_wo1 + (size_t)n0 * 1024;

    float acc[4][8][4] = {};
    GEMM_BODY(pA, pW)

    const int rbase = m0 + wm + (lane >> 2);
    const int cbase = n0 + wn + ((lane & 3) << 1);
    #pragma unroll
    for (int mi = 0; mi < 4; ++mi)
        #pragma unroll
        for (int ni = 0; ni < 8; ++ni) {
            int col = cbase + (ni << 3);
            float b0 = bias_s[col - n0], b1 = bias_s[col - n0 + 1];
            #pragma unroll
            for (int half = 0; half < 2; ++half) {
                int row = rbase + (mi << 4) + (half << 3);
                *reinterpret_cast<float2*>(&outf[(size_t)row * 1024 + col]) =
                    make_float2(acc[mi][ni][half*2] + b0,
                                acc[mi][ni][half*2+1] + b1);
            }
        }
}

// ---------------- tensor-core flash attention --------------------------------
// CTA = 64 q-rows, 128 threads, 2 CTAs/SM, 3-stage pipeline (R9 structure).
// S = (Qh+Ql) x K (2-term, exp2 domain); fixed-max softmax; O += P x V.
#define ATT_KV 16384
#define ATT_MB 1024
#define ATT_STAGE (2*ATT_KV + ATT_MB)            // K, V, maskbits = 33792
#define ATT_SMEM (3*ATT_STAGE)                   // 101376

__device__ __forceinline__ void att_stage(
    uint32_t sb, const __half* __restrict__ K, const __half* __restrict__ V,
    const uint32_t* __restrict__ Mb, int kt, int q0, int tid)
{
    #pragma unroll
    for (int i = 0; i < 8; ++i) {
        int seg = tid + (i << 7);
        int row = seg >> 3, cs = seg & 7;
        uint32_t so = row * 128 + ((cs << 4) ^ ((row & 7) << 4));
        size_t gofs = (size_t)((kt << 7) + row) * 64 + (cs << 3);
        cpa16(sb + so,          K + gofs);
        cpa16(sb + ATT_KV + so, V + gofs);
    }
    if (tid < 64)
        cpa16(sb + 2*ATT_KV + tid * 16,
              (const char*)(Mb + (size_t)(q0 + tid) * 64) + (kt << 4));
    CP_COMMIT();
}

__global__ __launch_bounds__(128, 2) void attn_tc()
{
    extern __shared__ __align__(128) char sm[];
    const int tid  = threadIdx.x;
    const int wid  = tid >> 5;
    const int lane = tid & 31;
    const int bh = blockIdx.y;
    const int b = bh >> 4, h = bh & 15;
    const int q0 = blockIdx.x << 6;

    const uint32_t smb = smem_u32(sm);

    const size_t hofs = (size_t)bh * 2048 * 64;
    const __half* gqh = g_qhi + hofs + (size_t)q0 * 64;
    const __half* gql = g_qlo + hofs + (size_t)q0 * 64;
    const __half* gk  = g_k1 + hofs;
    const __half* gv  = g_v1 + hofs;
    const uint32_t* gmb = g_mbits + (size_t)b * 2048 * 64;

    // ---- stage Q (hi, lo) through buffer 0, extract frags to registers ----
    #pragma unroll
    for (int i = 0; i < 4; ++i) {
        int seg = tid + (i << 7);
        int row = seg >> 3, cs = seg & 7;
        uint32_t so = row * 128 + ((cs << 4) ^ ((row & 7) << 4));
        size_t gofs = (size_t)row * 64 + (cs << 3);
        cpa16(smb + so,        gqh + gofs);
        cpa16(smb + 8192 + so, gql + gofs);
    }
    CP_COMMIT();
    CP_WAIT(0);
    __syncthreads();

    const int lr  = lane & 15;
    const int lxh = (lane >> 4) << 4;
    const int r   = lane >> 2;
    const int c2  = (lane & 3) << 1;

    uint32_t qh[4][4], ql[4][4];
    {
        int row = (wid << 4) + lr;
        uint32_t rb = smb + row * 128;
        uint32_t sw = (row & 7) << 4;
        #pragma unroll
        for (int kk = 0; kk < 4; ++kk) {
            uint32_t ad = rb + (((kk << 5) + lxh) ^ sw);
            LDSM4(qh[kk][0], qh[kk][1], qh[kk][2], qh[kk][3], ad);
            LDSM4(ql[kk][0], ql[kk][1], ql[kk][2], ql[kk][3], ad + 8192);
        }
    }
    __syncthreads();   // all warps done reading Q before stage 0 overwrite

    att_stage(smb,             gk, gv, gmb, 0, q0, tid);
    att_stage(smb + ATT_STAGE, gk, gv, gmb, 1, q0, tid);

    float o[8][4] = {};
    float l0 = 0.f, l1 = 0.f;
    const int qr0 = (wid << 4) + r;

    for (int kt = 0; kt < 16; ++kt) {
        if (kt < 15) { CP_WAIT(1); } else { CP_WAIT(0); }
        __syncthreads();
        if (kt + 2 < 16)
            att_stage(smb + ((kt + 2) % 3) * ATT_STAGE, gk, gv, gmb,
                      kt + 2, q0, tid);
        const uint32_t sb = smb + (kt % 3) * ATT_STAGE;
        const char* stp = sm + (kt % 3) * ATT_STAGE;

        // ---- S = (Qh + Ql) x K ----
        float sc[16][4];
        #pragma unroll
        for (int nt = 0; nt < 16; ++nt)
            #pragma unroll
            for (int j = 0; j < 4; ++j) sc[nt][j] = 0.f;

        #pragma unroll
        for (int g = 0; g < 8; ++g) {
            int krow = (g << 4) + lr;
            uint32_t rb = sb + krow * 128;
            uint32_t sw = (krow & 7) << 4;
            #pragma unroll
            for (int kk = 0; kk < 4; ++kk) {
                uint32_t ad = rb + (((kk << 5) + lxh) ^ sw);
                uint32_t k0r, k1r, k2r, k3r;
                LDSM4(k0r, k1r, k2r, k3r, ad);
                uint32_t bE[2] = {k0r, k2r}, bO[2] = {k1r, k3r};
                MMA16816(sc[2*g],   qh[kk], bE);
                MMA16816(sc[2*g+1], qh[kk], bO);
                MMA16816(sc[2*g],   ql[kk], bE);
                MMA16816(sc[2*g+1], ql[kk], bO);
            }
        }

        // ---- mask bits + fixed-max softmax (ex2 directly, masked -> 1.0) ----
        uint4 mv0 = *reinterpret_cast<const uint4*>(stp + 2*ATT_KV + qr0 * 16);
        uint4 mv1 = *reinterpret_cast<const uint4*>(stp + 2*ATT_KV + (qr0 + 8) * 16);
        uint32_t mw0[4] = {mv0.x, mv0.y, mv0.z, mv0.w};
        uint32_t mw1[4] = {mv1.x, mv1.y, mv1.z, mv1.w};

        float rs0 = 0.f, rs1 = 0.f;
        #pragma unroll
        for (int nt = 0; nt < 16; ++nt) {
            uint32_t w0 = mw0[nt >> 2], w1 = mw1[nt >> 2];
            int sh = ((nt & 3) << 3) + c2;
            float e;
            e = ((w0 >> sh) & 1u)       ? ex2f(sc[nt][0]) : 1.0f;
            sc[nt][0] = e; rs0 += e;
            e = ((w0 >> (sh + 1)) & 1u) ? ex2f(sc[nt][1]) : 1.0f;
            sc[nt][1] = e; rs0 += e;
            e = ((w1 >> sh) & 1u)       ? ex2f(sc[nt][2]) : 1.0f;
            sc[nt][2] = e; rs1 += e;
            e = ((w1 >> (sh + 1)) & 1u) ? ex2f(sc[nt][3]) : 1.0f;
            sc[nt][3] = e; rs1 += e;
        }
        rs0 += __shfl_xor_sync(~0u, rs0, 1); rs0 += __shfl_xor_sync(~0u, rs0, 2);
        rs1 += __shfl_xor_sync(~0u, rs1, 1); rs1 += __shfl_xor_sync(~0u, rs1, 2);
        l0 += rs0;
        l1 += rs1;

        // ---- O += P x V (single term) ----
        #pragma unroll
        for (int t = 0; t < 8; ++t) {
            uint32_t aP[4];
            #pragma unroll
            for (int u = 0; u < 4; ++u)
                aP[u] = pack_h2(sc[2*t + (u >> 1)][(u & 1) * 2],
                                sc[2*t + (u >> 1)][(u & 1) * 2 + 1]);
            int vrow = (t << 4) + lr;
            uint32_t rb = sb + ATT_KV + vrow * 128;
            uint32_t sw = (vrow & 7) << 4;
            #pragma unroll
            for (int dp = 0; dp < 4; ++dp) {
                uint32_t ad = rb + (((dp << 5) + lxh) ^ sw);
                uint32_t h0, h1, h2, h3;
                LDSM4T(h0, h1, h2, h3, ad);
                uint32_t bh0[2] = {h0, h1}, bh1[2] = {h2, h3};
                MMA16816(o[2*dp],   aP, bh0);
                MMA16816(o[2*dp+1], aP, bh1);
            }
        }
        __syncthreads();
    }

    // ---- epilogue: normalize, single fp16 store [B,S,1024] ----
    float i0 = 1.f / l0, i1 = 1.f / l1;
    int row0 = q0 + (wid << 4) + r;
    size_t base0 = ((size_t)(b * 2048) + row0) * 1024 + h * 64;
    size_t base1 = base0 + 8 * 1024;
    #pragma unroll
    for (int ni = 0; ni < 8; ++ni) {
        int d = (ni << 3) + c2;
        *reinterpret_cast<uint32_t*>(&g_ao1[base0 + d]) =
            pack_h2(o[ni][0] * i0, o[ni][1] * i0);
        *reinterpret_cast<uint32_t*>(&g_ao1[base1 + d]) =
            pack_h2(o[ni][2] * i1, o[ni][3] * i1);
    }
}

// ---------------------------------------------------------------------------
extern "C" void kernel_launch(void* const* d_in, const int* in_sizes, int n_in,
                              void* d_out, int out_size)
{
    const float* query = (const float*)d_in[0];
    const float* key_  = (const float*)d_in[1];
    const float* value = (const float*)d_in[2];
    const int*   mask  = (const int*)  d_in[3];
    const float* wq = (const float*)d_in[4];
    const float* bq = (const float*)d_in[5];
    const float* wk = (const float*)d_in[6];
    const float* bk = (const float*)d_in[7];
    const float* wv = (const float*)d_in[8];
    const float* bv = (const float*)d_in[9];
    const float* wo = (const float*)d_in[10];
    const float* bo = (const float*)d_in[11];

    void *paq, *pak, *pav, *pwq, *pwk, *pwv, *pwo, *pmb;
    cudaGetSymbolAddress(&paq, g_aq);
    cudaGetSymbolAddress(&pak, g_ak);
    cudaGetSymbolAddress(&pav, g_av);
    cudaGetSymbolAddress(&pwq, g_wq1);
    cudaGetSymbolAddress(&pwk, g_wk1);
    cudaGetSymbolAddress(&pwv, g_wv1);
    cudaGetSymbolAddress(&pwo, g_wo1);
    cudaGetSymbolAddress(&pmb, g_mbits);

    cudaFuncSetAttribute(gemm_qkv,
                         cudaFuncAttributeMaxDynamicSharedMemorySize, G_SMEM);
    cudaFuncSetAttribute(gemm_out,
                         cudaFuncAttributeMaxDynamicSharedMemorySize, G_SMEM);
    cudaFuncSetAttribute(attn_tc,
                         cudaFuncAttributeMaxDynamicSharedMemorySize, ATT_SMEM);

    conv_maskbits<<<65536, 256>>>(mask, (uint32_t*)pmb);
    conv_h1x3<<<dim3(8192, 3), 256>>>(
        (const float4*)query, (const float4*)key_, (const float4*)value,
        (uint2*)paq, (uint2*)pak, (uint2*)pav);
    conv_h1x4<<<dim3(1024, 4), 256>>>(
        (const float4*)wq, (const float4*)wk, (const float4*)wv,
        (const float4*)wo,
        (uint2*)pwq, (uint2*)pwk, (uint2*)pwv, (uint2*)pwo);

    gemm_qkv<<<dim3(8, 64, 3), 128, G_SMEM>>>(bq, bk, bv);
    attn_tc<<<dim3(32, 64), 128, ATT_SMEM>>>();
    gemm_out<<<dim3(8, 64), 128, G_SMEM>>>(bo, (float*)d_out);
}

// round 12
// speedup vs baseline: 1.1439x; 1.0197x over previous
#include <cuda_runtime.h>
#include <cuda_fp16.h>
#include <cstdint>

// ---------------- scratch (__device__ globals; no allocs allowed) -----------
__device__ __half g_aq[8192*1024];             // fp16 A inputs (single)
__device__ __half g_ak[8192*1024];
__device__ __half g_av[8192*1024];
__device__ __half g_ao1[8192*1024];            // attention out (single fp16)
__device__ __half g_wq1[1024*1024];            // weights single fp16
__device__ __half g_wk1[1024*1024];
__device__ __half g_wv1[1024*1024];
__device__ __half g_wo1[1024*1024];
__device__ __half g_qhi[4*16*2048*64];         // Q split (pre-scaled 0.125*log2e)
__device__ __half g_qlo[4*16*2048*64];
__device__ __half g_k1 [4*16*2048*64];         // K single
__device__ __half g_v1 [4*16*2048*64];         // V single
__device__ uint32_t g_mbits[4*2048*64];        // bit mask: 64 words per row

// ---------------- PTX helpers (generic ISA, valid at compute_103) -----------
__device__ __forceinline__ uint32_t smem_u32(const void* p) {
    uint32_t a;
    asm("{ .reg .u64 t; cvta.to.shared.u64 t, %1; cvt.u32.u64 %0, t; }"
        : "=r"(a) : "l"(p));
    return a;
}
__device__ __forceinline__ void cpa16(uint32_t dst, const void* src) {
    asm volatile("cp.async.cg.shared.global [%0], [%1], 16;"
                 :: "r"(dst), "l"(src) : "memory");
}
#define CP_COMMIT() asm volatile("cp.async.commit_group;" ::: "memory")
#define CP_WAIT(n)  asm volatile("cp.async.wait_group %0;" :: "n"(n) : "memory")

#define LDSM4(r0, r1, r2, r3, addr)                                          \
    asm volatile("ldmatrix.sync.aligned.m8n8.x4.shared.b16 {%0,%1,%2,%3}, [%4];" \
                 : "=r"(r0), "=r"(r1), "=r"(r2), "=r"(r3) : "r"(addr))
#define LDSM4T(r0, r1, r2, r3, addr)                                         \
    asm volatile("ldmatrix.sync.aligned.m8n8.x4.trans.shared.b16 {%0,%1,%2,%3}, [%4];" \
                 : "=r"(r0), "=r"(r1), "=r"(r2), "=r"(r3) : "r"(addr))

#define MMA16816(d, a, b)                                                    \
    asm volatile("mma.sync.aligned.m16n8k16.row.col.f32.f16.f16.f32 "        \
                 "{%0,%1,%2,%3}, {%4,%5,%6,%7}, {%8,%9}, {%0,%1,%2,%3};"     \
                 : "+f"((d)[0]), "+f"((d)[1]), "+f"((d)[2]), "+f"((d)[3])    \
                 : "r"((a)[0]), "r"((a)[1]), "r"((a)[2]), "r"((a)[3]),       \
                   "r"((b)[0]), "r"((b)[1]))

__device__ __forceinline__ uint32_t pack_h2(float a, float b) {
    __half2 h = __floats2half2_rn(a, b);
    return *reinterpret_cast<uint32_t*>(&h);
}
__device__ __forceinline__ float ex2f(float x) {
    float r;
    asm("ex2.approx.f32 %0, %1;" : "=f"(r) : "f"(x));
    return r;
}

// ---------------- conversions (fused launches) -------------------------------
__global__ __launch_bounds__(256) void conv_h1x3(
    const float4* __restrict__ s0, const float4* __restrict__ s1,
    const float4* __restrict__ s2, uint2* __restrict__ d0,
    uint2* __restrict__ d1, uint2* __restrict__ d2)
{
    int z = blockIdx.y;
    const float4* src = (z == 0) ? s0 : (z == 1) ? s1 : s2;
    uint2* dst = (z == 0) ? d0 : (z == 1) ? d1 : d2;
    int i = blockIdx.x * blockDim.x + threadIdx.x;
    float4 v = src[i];
    dst[i] = make_uint2(pack_h2(v.x, v.y), pack_h2(v.z, v.w));
}

__global__ __launch_bounds__(256) void conv_h1x4(
    const float4* __restrict__ s0, const float4* __restrict__ s1,
    const float4* __restrict__ s2, const float4* __restrict__ s3,
    uint2* __restrict__ d0, uint2* __restrict__ d1,
    uint2* __restrict__ d2, uint2* __restrict__ d3)
{
    int z = blockIdx.y;
    const float4* src = (z == 0) ? s0 : (z == 1) ? s1 : (z == 2) ? s2 : s3;
    uint2* dst = (z == 0) ? d0 : (z == 1) ? d1 : (z == 2) ? d2 : d3;
    int i = blockIdx.x * blockDim.x + threadIdx.x;
    float4 v = src[i];
    dst[i] = make_uint2(pack_h2(v.x, v.y), pack_h2(v.z, v.w));
}

__global__ __launch_bounds__(256) void conv_maskbits(
    const int* __restrict__ src, uint32_t* __restrict__ dst)
{
    int gw = (blockIdx.x * blockDim.x + threadIdx.x) >> 5;
    int lane = threadIdx.x & 31;
    int v = src[(size_t)gw * 32 + lane];
    uint32_t b = __ballot_sync(0xffffffffu, v != 0);
    if (lane == 0) dst[gw] = b;
}

// ---------------- fp16 single-term GEMM core (mma.sync) ---------------------
// C = A(fp16) @ W(fp16)^T. CTA 128x128, BK=64, 3-stage cp.async, 2 CTAs/SM.
#define G_MAT 16384
#define G_STAGE (2 * G_MAT)                  // A, W = 32768
#define G_SMEM (3 * G_STAGE)                 // 98304

__device__ __forceinline__ void g_stage2(
    uint32_t sb, const __half* __restrict__ pA, const __half* __restrict__ pW,
    int kt, int tid)
{
    const __half* srcs[2] = {pA, pW};
    #pragma unroll
    for (int m = 0; m < 2; ++m) {
        uint32_t mb = sb + m * G_MAT;
        const __half* sp = srcs[m];
        #pragma unroll
        for (int i = 0; i < 8; ++i) {
            int seg = tid + (i << 7);
            int row = seg >> 3, cs = seg & 7;
            cpa16(mb + row * 128 + ((cs << 4) ^ ((row & 7) << 4)),
                  sp + (size_t)row * 1024 + (kt << 6) + (cs << 3));
        }
    }
    CP_COMMIT();
}

#define GLOAD(buf, kk, sb)                                                   \
    do {                                                                     \
        const int x_ = ((kk) << 5) + lxh;                                    \
        _Pragma("unroll")                                                    \
        for (int mi = 0; mi < 4; ++mi) {                                     \
            int row = wm + (mi << 4) + lr;                                   \
            uint32_t ad = (sb) + row * 128 + (x_ ^ ((row & 7) << 4));        \
            LDSM4(af[buf][mi][0], af[buf][mi][1], af[buf][mi][2],            \
                  af[buf][mi][3], ad);                                       \
        }                                                                    \
        _Pragma("unroll")                                                    \
        for (int g = 0; g < 4; ++g) {                                        \
            int row = wn + (g << 4) + lr;                                    \
            uint32_t wd = (sb) + G_MAT + row * 128 + (x_ ^ ((row & 7) << 4));\
            uint32_t r0, r1, r2, r3;                                         \
            LDSM4(r0, r1, r2, r3, wd);                                       \
            wf[buf][2*g][0] = r0; wf[buf][2*g][1] = r2;                      \
            wf[buf][2*g+1][0] = r1; wf[buf][2*g+1][1] = r3;                  \
        }                                                                    \
    } while (0)

#define GEMM_BODY(pA, pW)                                                    \
    g_stage2(sb0,           (pA), (pW), 0, tid);                             \
    g_stage2(sb0 + G_STAGE, (pA), (pW), 1, tid);                             \
    uint32_t af[2][4][4], wf[2][8][2];                                       \
    for (int j = 0; j < 16; ++j) {                                           \
        if (j < 15) { CP_WAIT(1); } else { CP_WAIT(0); }                     \
        __syncthreads();                                                     \
        if (j + 2 < 16)                                                      \
            g_stage2(sb0 + ((j + 2) % 3) * G_STAGE, (pA), (pW), j + 2, tid); \
        const uint32_t sb = sb0 + (j % 3) * G_STAGE;                         \
        GLOAD(0, 0, sb);                                                     \
        _Pragma("unroll")                                                    \
        for (int kk = 0; kk < 4; ++kk) {                                     \
            if (kk < 3) GLOAD((kk + 1) & 1, kk + 1, sb);                     \
            const int cb = kk & 1;                                           \
            _Pragma("unroll")                                                \
            for (int mi = 0; mi < 4; ++mi)                                   \
                _Pragma("unroll")                                            \
                for (int ni = 0; ni < 8; ++ni)                               \
                    MMA16816(acc[mi][ni], af[cb][mi], wf[cb][ni]);           \
        }                                                                    \
    }

__global__ __launch_bounds__(128, 2) void gemm_qkv(
    const float* __restrict__ bq, const float* __restrict__ bk,
    const float* __restrict__ bv)
{
    extern __shared__ __align__(128) char dynsm[];
    __shared__ float bias_s[128];

    const int tid  = threadIdx.x;
    const int wid  = tid >> 5;
    const int lane = tid & 31;
    const int m0 = blockIdx.y << 7;
    const int n0 = blockIdx.x << 7;
    const int z  = blockIdx.z;
    const int wm = (wid >> 1) << 6;     // 0 or 64
    const int wn = (wid & 1) << 6;      // 0 or 64
    const int lr = lane & 15;
    const int lxh = (lane >> 4) << 4;

    const __half* A = (z == 0) ? g_aq  : (z == 1) ? g_ak  : g_av;
    const __half* W = (z == 0) ? g_wq1 : (z == 1) ? g_wk1 : g_wv1;
    const float* bias = (z == 0) ? bq : (z == 1) ? bk : bv;

    bias_s[tid] = bias[n0 + tid];

    const uint32_t sb0 = smem_u32(dynsm);
    const __half* pA = A + (size_t)m0 * 1024;
    const __half* pW = W + (size_t)n0 * 1024;

    float acc[4][8][4] = {};
    GEMM_BODY(pA, pW)

    // epilogue: scatter [B,H,S,dk]; z=0 Q split (pre-scaled 0.125*log2e), z=1 K, z=2 V
    const int rbase = m0 + wm + (lane >> 2);
    const int cbase = n0 + wn + ((lane & 3) << 1);
    #pragma unroll
    for (int mi = 0; mi < 4; ++mi) {
        #pragma unroll
        for (int ni = 0; ni < 8; ++ni) {
            int col = cbase + (ni << 3);
            float b0 = bias_s[col - n0], b1 = bias_s[col - n0 + 1];
            #pragma unroll
            for (int half = 0; half < 2; ++half) {
                int row = rbase + (mi << 4) + (half << 3);
                float v0 = acc[mi][ni][half*2]   + b0;
                float v1 = acc[mi][ni][half*2+1] + b1;
                int h = col >> 6, d = col & 63;
                int bb = row >> 11, s = row & 2047;
                size_t idx = ((size_t)((bb << 4) + h) * 2048 + s) * 64 + d;
                if (z == 0) {
                    v0 *= 0.18033688f; v1 *= 0.18033688f;   // 0.125 * log2(e)
                    __half h0 = __float2half_rn(v0), h1 = __float2half_rn(v1);
                    uint32_t hi = (uint32_t)*reinterpret_cast<uint16_t*>(&h0) |
                                  ((uint32_t)*reinterpret_cast<uint16_t*>(&h1) << 16);
                    uint32_t lo = pack_h2(v0 - __half2float(h0),
                                          v1 - __half2float(h1));
                    *reinterpret_cast<uint32_t*>(&g_qhi[idx]) = hi;
                    *reinterpret_cast<uint32_t*>(&g_qlo[idx]) = lo;
                } else if (z == 1) {
                    *reinterpret_cast<uint32_t*>(&g_k1[idx]) = pack_h2(v0, v1);
                } else {
                    *reinterpret_cast<uint32_t*>(&g_v1[idx]) = pack_h2(v0, v1);
                }
            }
        }
    }
}

__global__ __launch_bounds__(128, 2) void gemm_out(
    const float* __restrict__ bo, float* __restrict__ outf)
{
    extern __shared__ __align__(128) char dynsm[];
    __shared__ float bias_s[128];

    const int tid  = threadIdx.x;
    const int wid  = tid >> 5;
    const int lane = tid & 31;
    const int m0 = blockIdx.y << 7;
    const int n0 = blockIdx.x << 7;
    const int wm = (wid >> 1) << 6;
    const int wn = (wid & 1) << 6;
    const int lr = lane & 15;
    const int lxh = (lane >> 4) << 4;

    bias_s[tid] = bo[n0 + tid];

    const uint32_t sb0 = smem_u32(dynsm);
    const __half* pA = g_ao1 + (size_t)m0 * 1024;
    const __half* pW = g_wo1 + (size_t)n0 * 1024;

    float acc[4][8][4] = {};
    GEMM_BODY(pA, pW)

    const int rbase = m0 + wm + (lane >> 2);
    const int cbase = n0 + wn + ((lane & 3) << 1);
    #pragma unroll
    for (int mi = 0; mi < 4; ++mi)
        #pragma unroll
        for (int ni = 0; ni < 8; ++ni) {
            int col = cbase + (ni << 3);
            float b0 = bias_s[col - n0], b1 = bias_s[col - n0 + 1];
            #pragma unroll
            for (int half = 0; half < 2; ++half) {
                int row = rbase + (mi << 4) + (half << 3);
                *reinterpret_cast<float2*>(&outf[(size_t)row * 1024 + col]) =
                    make_float2(acc[mi][ni][half*2] + b0,
                                acc[mi][ni][half*2+1] + b1);
            }
        }
}

// ---------------- tensor-core flash attention --------------------------------
// CTA = 64 q-rows, 128 threads, 3 CTAs/SM, 2-stage pipeline.
// S = (Qh+Ql) x K computed in two 64-col halves (reg diet); fixed-max softmax
// (ex2, masked->1.0); row-sum l via ones-MMA on the tensor pipe; O += P x V.
#define ATT_KV 16384
#define ATT_MB 1024
#define ATT_STAGE (2*ATT_KV + ATT_MB)            // K, V, maskbits = 33792
#define ATT_SMEM (2*ATT_STAGE)                   // 67584

__device__ __forceinline__ void att_stage(
    uint32_t sb, const __half* __restrict__ K, const __half* __restrict__ V,
    const uint32_t* __restrict__ Mb, int kt, int q0, int tid)
{
    #pragma unroll
    for (int i = 0; i < 8; ++i) {
        int seg = tid + (i << 7);
        int row = seg >> 3, cs = seg & 7;
        uint32_t so = row * 128 + ((cs << 4) ^ ((row & 7) << 4));
        size_t gofs = (size_t)((kt << 7) + row) * 64 + (cs << 3);
        cpa16(sb + so,          K + gofs);
        cpa16(sb + ATT_KV + so, V + gofs);
    }
    if (tid < 64)
        cpa16(sb + 2*ATT_KV + tid * 16,
              (const char*)(Mb + (size_t)(q0 + tid) * 64) + (kt << 4));
    CP_COMMIT();
}

__global__ __launch_bounds__(128, 3) void attn_tc()
{
    extern __shared__ __align__(128) char sm[];
    const int tid  = threadIdx.x;
    const int wid  = tid >> 5;
    const int lane = tid & 31;
    const int bh = blockIdx.y;
    const int b = bh >> 4, h = bh & 15;
    const int q0 = blockIdx.x << 6;

    const uint32_t smb = smem_u32(sm);

    const size_t hofs = (size_t)bh * 2048 * 64;
    const __half* gqh = g_qhi + hofs + (size_t)q0 * 64;
    const __half* gql = g_qlo + hofs + (size_t)q0 * 64;
    const __half* gk  = g_k1 + hofs;
    const __half* gv  = g_v1 + hofs;
    const uint32_t* gmb = g_mbits + (size_t)b * 2048 * 64;

    // ---- stage Q (hi, lo) through buffer 0, extract frags to registers ----
    #pragma unroll
    for (int i = 0; i < 4; ++i) {
        int seg = tid + (i << 7);
        int row = seg >> 3, cs = seg & 7;
        uint32_t so = row * 128 + ((cs << 4) ^ ((row & 7) << 4));
        size_t gofs = (size_t)row * 64 + (cs << 3);
        cpa16(smb + so,        gqh + gofs);
        cpa16(smb + 8192 + so, gql + gofs);
    }
    CP_COMMIT();
    CP_WAIT(0);
    __syncthreads();

    const int lr  = lane & 15;
    const int lxh = (lane >> 4) << 4;
    const int r   = lane >> 2;
    const int c2  = (lane & 3) << 1;

    uint32_t qh[4][4], ql[4][4];
    {
        int row = (wid << 4) + lr;
        uint32_t rb = smb + row * 128;
        uint32_t sw = (row & 7) << 4;
        #pragma unroll
        for (int kk = 0; kk < 4; ++kk) {
            uint32_t ad = rb + (((kk << 5) + lxh) ^ sw);
            LDSM4(qh[kk][0], qh[kk][1], qh[kk][2], qh[kk][3], ad);
            LDSM4(ql[kk][0], ql[kk][1], ql[kk][2], ql[kk][3], ad + 8192);
        }
    }
    __syncthreads();   // all warps done reading Q before stage 0 overwrite

    att_stage(smb,             gk, gv, gmb, 0, q0, tid);
    att_stage(smb + ATT_STAGE, gk, gv, gmb, 1, q0, tid);

    float o[8][4] = {};
    float lacc[2][4] = {};
    const uint32_t ones[2] = {0x3C003C00u, 0x3C003C00u};
    const int qr0 = (wid << 4) + r;

    for (int kt = 0; kt < 16; ++kt) {
        if (kt < 15) { CP_WAIT(1); } else { CP_WAIT(0); }
        __syncthreads();
        const uint32_t sb = smb + (kt & 1) * ATT_STAGE;
        const char* stp = sm + (kt & 1) * ATT_STAGE;

        uint32_t P[32];

        // ---- S = (Qh + Ql) x K, two 64-col halves (reg pressure) ----
        #pragma unroll
        for (int half = 0; half < 2; ++half) {
            float sc[8][4];
            #pragma unroll
            for (int nt = 0; nt < 8; ++nt)
                #pragma unroll
                for (int j = 0; j < 4; ++j) sc[nt][j] = 0.f;

            #pragma unroll
            for (int hg = 0; hg < 4; ++hg) {
                int g = (half << 2) + hg;
                int krow = (g << 4) + lr;
                uint32_t rb = sb + krow * 128;
                uint32_t sw = (krow & 7) << 4;
                #pragma unroll
                for (int kk = 0; kk < 4; ++kk) {
                    uint32_t ad = rb + (((kk << 5) + lxh) ^ sw);
                    uint32_t k0r, k1r, k2r, k3r;
                    LDSM4(k0r, k1r, k2r, k3r, ad);
                    uint32_t bE[2] = {k0r, k2r}, bO[2] = {k1r, k3r};
                    MMA16816(sc[2*hg],   qh[kk], bE);
                    MMA16816(sc[2*hg+1], qh[kk], bO);
                    MMA16816(sc[2*hg],   ql[kk], bE);
                    MMA16816(sc[2*hg+1], ql[kk], bO);
                }
            }

            // ---- mask bits + fixed-max exp + pack to fp16x2 ----
            uint2 mA = *reinterpret_cast<const uint2*>(
                stp + 2*ATT_KV + qr0 * 16 + (half << 3));
            uint2 mB = *reinterpret_cast<const uint2*>(
                stp + 2*ATT_KV + (qr0 + 8) * 16 + (half << 3));
            uint32_t mw0[2] = {mA.x, mA.y};
            uint32_t mw1[2] = {mB.x, mB.y};

            #pragma unroll
            for (int nt = 0; nt < 8; ++nt) {
                uint32_t w0 = mw0[nt >> 2], w1 = mw1[nt >> 2];
                int sh = ((nt & 3) << 3) + c2;
                float e0 = ((w0 >> sh) & 1u)       ? ex2f(sc[nt][0]) : 1.0f;
                float e1 = ((w0 >> (sh + 1)) & 1u) ? ex2f(sc[nt][1]) : 1.0f;
                float e2 = ((w1 >> sh) & 1u)       ? ex2f(sc[nt][2]) : 1.0f;
                float e3 = ((w1 >> (sh + 1)) & 1u) ? ex2f(sc[nt][3]) : 1.0f;
                int base = (half << 4) + (nt << 1);
                P[base]     = pack_h2(e0, e1);
                P[base + 1] = pack_h2(e2, e3);
            }
        }

        // ---- row sums on the tensor pipe: lacc += P x ones ----
        #pragma unroll
        for (int t = 0; t < 8; ++t)
            MMA16816(lacc[t & 1], &P[t << 2], ones);

        // ---- O += P x V (single term) ----
        #pragma unroll
        for (int t = 0; t < 8; ++t) {
            int vrow = (t << 4) + lr;
            uint32_t rb = sb + ATT_KV + vrow * 128;
            uint32_t sw = (vrow & 7) << 4;
            #pragma unroll
            for (int dp = 0; dp < 4; ++dp) {
                uint32_t ad = rb + (((dp << 5) + lxh) ^ sw);
                uint32_t h0, h1, h2, h3;
                LDSM4T(h0, h1, h2, h3, ad);
                uint32_t bh0[2] = {h0, h1}, bh1[2] = {h2, h3};
                MMA16816(o[2*dp],   &P[t << 2], bh0);
                MMA16816(o[2*dp+1], &P[t << 2], bh1);
            }
        }

        __syncthreads();   // all warps done reading stage kt
        if (kt + 2 < 16)
            att_stage(smb + (kt & 1) * ATT_STAGE, gk, gv, gmb, kt + 2, q0, tid);
    }

    // ---- epilogue: normalize (l from ones-MMA), store [B,S,1024] fp16 ----
    float l0 = lacc[0][0] + lacc[1][0];
    float l1 = lacc[0][2] + lacc[1][2];
    float i0 = 1.f / l0, i1 = 1.f / l1;
    int row0 = q0 + (wid << 4) + r;
    size_t base0 = ((size_t)(b * 2048) + row0) * 1024 + h * 64;
    size_t base1 = base0 + 8 * 1024;
    #pragma unroll
    for (int ni = 0; ni < 8; ++ni) {
        int d = (ni << 3) + c2;
        *reinterpret_cast<uint32_t*>(&g_ao1[base0 + d]) =
            pack_h2(o[ni][0] * i0, o[ni][1] * i0);
        *reinterpret_cast<uint32_t*>(&g_ao1[base1 + d]) =
            pack_h2(o[ni][2] * i1, o[ni][3] * i1);
    }
}

// ---------------------------------------------------------------------------
extern "C" void kernel_launch(void* const* d_in, const int* in_sizes, int n_in,
                              void* d_out, int out_size)
{
    const float* query = (const float*)d_in[0];
    const float* key_  = (const float*)d_in[1];
    const float* value = (const float*)d_in[2];
    const int*   mask  = (const int*)  d_in[3];
    const float* wq = (const float*)d_in[4];
    const float* bq = (const float*)d_in[5];
    const float* wk = (const float*)d_in[6];
    const float* bk = (const float*)d_in[7];
    const float* wv = (const float*)d_in[8];
    const float* bv = (const float*)d_in[9];
    const float* wo = (const float*)d_in[10];
    const float* bo = (const float*)d_in[11];

    void *paq, *pak, *pav, *pwq, *pwk, *pwv, *pwo, *pmb;
    cudaGetSymbolAddress(&paq, g_aq);
    cudaGetSymbolAddress(&pak, g_ak);
    cudaGetSymbolAddress(&pav, g_av);
    cudaGetSymbolAddress(&pwq, g_wq1);
    cudaGetSymbolAddress(&pwk, g_wk1);
    cudaGetSymbolAddress(&pwv, g_wv1);
    cudaGetSymbolAddress(&pwo, g_wo1);
    cudaGetSymbolAddress(&pmb, g_mbits);

    cudaFuncSetAttribute(gemm_qkv,
                         cudaFuncAttributeMaxDynamicSharedMemorySize, G_SMEM);
    cudaFuncSetAttribute(gemm_out,
                         cudaFuncAttributeMaxDynamicSharedMemorySize, G_SMEM);
    cudaFuncSetAttribute(attn_tc,
                         cudaFuncAttributeMaxDynamicSharedMemorySize, ATT_SMEM);

    conv_maskbits<<<65536, 256>>>(mask, (uint32_t*)pmb);
    conv_h1x3<<<dim3(8192, 3), 256>>>(
        (const float4*)query, (const float4*)key_, (const float4*)value,
        (uint2*)paq, (uint2*)pak, (uint2*)pav);
    conv_h1x4<<<dim3(1024, 4), 256>>>(
        (const float4*)wq, (const float4*)wk, (const float4*)wv,
        (const float4*)wo,
        (uint2*)pwq, (uint2*)pwk, (uint2*)pwv, (uint2*)pwo);

    gemm_qkv<<<dim3(8, 64, 3), 128, G_SMEM>>>(bq, bk, bv);
    attn_tc<<<dim3(32, 64), 128, ATT_SMEM>>>();
    gemm_out<<<dim3(8, 64), 128, G_SMEM>>>(bo, (float*)d_out);
}

// round 13
// speedup vs baseline: 1.2136x; 1.0609x over previous
#include <cuda_runtime.h>
#include <cuda_fp16.h>
#include <cstdint>

// ---------------- scratch (__device__ globals; no allocs allowed) -----------
__device__ __half g_aq[8192*1024];             // fp16 A inputs (single)
__device__ __half g_ak[8192*1024];
__device__ __half g_av[8192*1024];
__device__ __half g_ao1[8192*1024];            // attention out (single fp16)
__device__ __half g_wq1[1024*1024];            // weights single fp16
__device__ __half g_wk1[1024*1024];
__device__ __half g_wv1[1024*1024];
__device__ __half g_wo1[1024*1024];
__device__ __half g_q1 [4*16*2048*64];         // Q single (pre-scaled 0.125*log2e)
__device__ __half g_k1 [4*16*2048*64];         // K single
__device__ __half g_v1 [4*16*2048*64];         // V single
__device__ uint32_t g_mbits[4*2048*64];        // bit mask: 64 words per row

// ---------------- PTX helpers (generic ISA, valid at compute_103) -----------
__device__ __forceinline__ uint32_t smem_u32(const void* p) {
    uint32_t a;
    asm("{ .reg .u64 t; cvta.to.shared.u64 t, %1; cvt.u32.u64 %0, t; }"
        : "=r"(a) : "l"(p));
    return a;
}
__device__ __forceinline__ void cpa16(uint32_t dst, const void* src) {
    asm volatile("cp.async.cg.shared.global [%0], [%1], 16;"
                 :: "r"(dst), "l"(src) : "memory");
}
#define CP_COMMIT() asm volatile("cp.async.commit_group;" ::: "memory")
#define CP_WAIT(n)  asm volatile("cp.async.wait_group %0;" :: "n"(n) : "memory")

#define LDSM4(r0, r1, r2, r3, addr)                                          \
    asm volatile("ldmatrix.sync.aligned.m8n8.x4.shared.b16 {%0,%1,%2,%3}, [%4];" \
                 : "=r"(r0), "=r"(r1), "=r"(r2), "=r"(r3) : "r"(addr))
#define LDSM4T(r0, r1, r2, r3, addr)                                         \
    asm volatile("ldmatrix.sync.aligned.m8n8.x4.trans.shared.b16 {%0,%1,%2,%3}, [%4];" \
                 : "=r"(r0), "=r"(r1), "=r"(r2), "=r"(r3) : "r"(addr))

#define MMA16816(d, a, b)                                                    \
    asm volatile("mma.sync.aligned.m16n8k16.row.col.f32.f16.f16.f32 "        \
                 "{%0,%1,%2,%3}, {%4,%5,%6,%7}, {%8,%9}, {%0,%1,%2,%3};"     \
                 : "+f"((d)[0]), "+f"((d)[1]), "+f"((d)[2]), "+f"((d)[3])    \
                 : "r"((a)[0]), "r"((a)[1]), "r"((a)[2]), "r"((a)[3]),       \
                   "r"((b)[0]), "r"((b)[1]))

__device__ __forceinline__ uint32_t pack_h2(float a, float b) {
    __half2 h = __floats2half2_rn(a, b);
    return *reinterpret_cast<uint32_t*>(&h);
}
__device__ __forceinline__ float ex2f(float x) {
    float r;
    asm("ex2.approx.f32 %0, %1;" : "=f"(r) : "f"(x));
    return r;
}

// ---------------- conversions (fused launches) -------------------------------
__global__ __launch_bounds__(256) void conv_h1x3(
    const float4* __restrict__ s0, const float4* __restrict__ s1,
    const float4* __restrict__ s2, uint2* __restrict__ d0,
    uint2* __restrict__ d1, uint2* __restrict__ d2)
{
    int z = blockIdx.y;
    const float4* src = (z == 0) ? s0 : (z == 1) ? s1 : s2;
    uint2* dst = (z == 0) ? d0 : (z == 1) ? d1 : d2;
    int i = blockIdx.x * blockDim.x + threadIdx.x;
    float4 v = src[i];
    dst[i] = make_uint2(pack_h2(v.x, v.y), pack_h2(v.z, v.w));
}

__global__ __launch_bounds__(256) void conv_h1x4(
    const float4* __restrict__ s0, const float4* __restrict__ s1,
    const float4* __restrict__ s2, const float4* __restrict__ s3,
    uint2* __restrict__ d0, uint2* __restrict__ d1,
    uint2* __restrict__ d2, uint2* __restrict__ d3)
{
    int z = blockIdx.y;
    const float4* src = (z == 0) ? s0 : (z == 1) ? s1 : (z == 2) ? s2 : s3;
    uint2* dst = (z == 0) ? d0 : (z == 1) ? d1 : (z == 2) ? d2 : d3;
    int i = blockIdx.x * blockDim.x + threadIdx.x;
    float4 v = src[i];
    dst[i] = make_uint2(pack_h2(v.x, v.y), pack_h2(v.z, v.w));
}

__global__ __launch_bounds__(256) void conv_maskbits(
    const int* __restrict__ src, uint32_t* __restrict__ dst)
{
    int gw = (blockIdx.x * blockDim.x + threadIdx.x) >> 5;
    int lane = threadIdx.x & 31;
    int v = src[(size_t)gw * 32 + lane];
    uint32_t b = __ballot_sync(0xffffffffu, v != 0);
    if (lane == 0) dst[gw] = b;
}

// ---------------- fp16 single-term GEMM core (mma.sync) ---------------------
// C = A(fp16) @ W(fp16)^T. CTA 128x128, BK=64, 3-stage cp.async, 2 CTAs/SM.
#define G_MAT 16384
#define G_STAGE (2 * G_MAT)                  // A, W = 32768
#define G_SMEM (3 * G_STAGE)                 // 98304

__device__ __forceinline__ void g_stage2(
    uint32_t sb, const __half* __restrict__ pA, const __half* __restrict__ pW,
    int kt, int tid)
{
    const __half* srcs[2] = {pA, pW};
    #pragma unroll
    for (int m = 0; m < 2; ++m) {
        uint32_t mb = sb + m * G_MAT;
        const __half* sp = srcs[m];
        #pragma unroll
        for (int i = 0; i < 8; ++i) {
            int seg = tid + (i << 7);
            int row = seg >> 3, cs = seg & 7;
            cpa16(mb + row * 128 + ((cs << 4) ^ ((row & 7) << 4)),
                  sp + (size_t)row * 1024 + (kt << 6) + (cs << 3));
        }
    }
    CP_COMMIT();
}

#define GLOAD(buf, kk, sb)                                                   \
    do {                                                                     \
        const int x_ = ((kk) << 5) + lxh;                                    \
        _Pragma("unroll")                                                    \
        for (int mi = 0; mi < 4; ++mi) {                                     \
            int row = wm + (mi << 4) + lr;                                   \
            uint32_t ad = (sb) + row * 128 + (x_ ^ ((row & 7) << 4));        \
            LDSM4(af[buf][mi][0], af[buf][mi][1], af[buf][mi][2],            \
                  af[buf][mi][3], ad);                                       \
        }                                                                    \
        _Pragma("unroll")                                                    \
        for (int g = 0; g < 4; ++g) {                                        \
            int row = wn + (g << 4) + lr;                                    \
            uint32_t wd = (sb) + G_MAT + row * 128 + (x_ ^ ((row & 7) << 4));\
            uint32_t r0, r1, r2, r3;                                         \
            LDSM4(r0, r1, r2, r3, wd);                                       \
            wf[buf][2*g][0] = r0; wf[buf][2*g][1] = r2;                      \
            wf[buf][2*g+1][0] = r1; wf[buf][2*g+1][1] = r3;                  \
        }                                                                    \
    } while (0)

#define GEMM_BODY(pA, pW)                                                    \
    g_stage2(sb0,           (pA), (pW), 0, tid);                             \
    g_stage2(sb0 + G_STAGE, (pA), (pW), 1, tid);                             \
    uint32_t af[2][4][4], wf[2][8][2];                                       \
    for (int j = 0; j < 16; ++j) {                                           \
        if (j < 15) { CP_WAIT(1); } else { CP_WAIT(0); }                     \
        __syncthreads();                                                     \
        if (j + 2 < 16)                                                      \
            g_stage2(sb0 + ((j + 2) % 3) * G_STAGE, (pA), (pW), j + 2, tid); \
        const uint32_t sb = sb0 + (j % 3) * G_STAGE;                         \
        GLOAD(0, 0, sb);                                                     \
        _Pragma("unroll")                                                    \
        for (int kk = 0; kk < 4; ++kk) {                                     \
            if (kk < 3) GLOAD((kk + 1) & 1, kk + 1, sb);                     \
            const int cb = kk & 1;                                           \
            _Pragma("unroll")                                                \
            for (int mi = 0; mi < 4; ++mi)                                   \
                _Pragma("unroll")                                            \
                for (int ni = 0; ni < 8; ++ni)                               \
                    MMA16816(acc[mi][ni], af[cb][mi], wf[cb][ni]);           \
        }                                                                    \
    }

__global__ __launch_bounds__(128, 2) void gemm_qkv(
    const float* __restrict__ bq, const float* __restrict__ bk,
    const float* __restrict__ bv)
{
    extern __shared__ __align__(128) char dynsm[];
    __shared__ float bias_s[128];

    const int tid  = threadIdx.x;
    const int wid  = tid >> 5;
    const int lane = tid & 31;
    const int m0 = blockIdx.y << 7;
    const int n0 = blockIdx.x << 7;
    const int z  = blockIdx.z;
    const int wm = (wid >> 1) << 6;     // 0 or 64
    const int wn = (wid & 1) << 6;      // 0 or 64
    const int lr = lane & 15;
    const int lxh = (lane >> 4) << 4;

    const __half* A = (z == 0) ? g_aq  : (z == 1) ? g_ak  : g_av;
    const __half* W = (z == 0) ? g_wq1 : (z == 1) ? g_wk1 : g_wv1;
    const float* bias = (z == 0) ? bq : (z == 1) ? bk : bv;

    bias_s[tid] = bias[n0 + tid];

    const uint32_t sb0 = smem_u32(dynsm);
    const __half* pA = A + (size_t)m0 * 1024;
    const __half* pW = W + (size_t)n0 * 1024;

    float acc[4][8][4] = {};
    GEMM_BODY(pA, pW)

    // epilogue: scatter [B,H,S,dk]; z=0 Q (pre-scaled 0.125*log2e), z=1 K, z=2 V
    const int rbase = m0 + wm + (lane >> 2);
    const int cbase = n0 + wn + ((lane & 3) << 1);
    #pragma unroll
    for (int mi = 0; mi < 4; ++mi) {
        #pragma unroll
        for (int ni = 0; ni < 8; ++ni) {
            int col = cbase + (ni << 3);
            float b0 = bias_s[col - n0], b1 = bias_s[col - n0 + 1];
            #pragma unroll
            for (int half = 0; half < 2; ++half) {
                int row = rbase + (mi << 4) + (half << 3);
                float v0 = acc[mi][ni][half*2]   + b0;
                float v1 = acc[mi][ni][half*2+1] + b1;
                int h = col >> 6, d = col & 63;
                int bb = row >> 11, s = row & 2047;
                size_t idx = ((size_t)((bb << 4) + h) * 2048 + s) * 64 + d;
                if (z == 0) {
                    v0 *= 0.18033688f; v1 *= 0.18033688f;   // 0.125 * log2(e)
                    *reinterpret_cast<uint32_t*>(&g_q1[idx]) = pack_h2(v0, v1);
                } else if (z == 1) {
                    *reinterpret_cast<uint32_t*>(&g_k1[idx]) = pack_h2(v0, v1);
                } else {
                    *reinterpret_cast<uint32_t*>(&g_v1[idx]) = pack_h2(v0, v1);
                }
            }
        }
    }
}

__global__ __launch_bounds__(128, 2) void gemm_out(
    const float* __restrict__ bo, float* __restrict__ outf)
{
    extern __shared__ __align__(128) char dynsm[];
    __shared__ float bias_s[128];

    const int tid  = threadIdx.x;
    const int wid  = tid >> 5;
    const int lane = tid & 31;
    const int m0 = blockIdx.y << 7;
    const int n0 = blockIdx.x << 7;
    const int wm = (wid >> 1) << 6;
    const int wn = (wid & 1) << 6;
    const int lr = lane & 15;
    const int lxh = (lane >> 4) << 4;

    bias_s[tid] = bo[n0 + tid];

    const uint32_t sb0 = smem_u32(dynsm);
    const __half* pA = g_ao1 + (size_t)m0 * 1024;
    const __half* pW = g_wo1 + (size_t)n0 * 1024;

    float acc[4][8][4] = {};
    GEMM_BODY(pA, pW)

    const int rbase = m0 + wm + (lane >> 2);
    const int cbase = n0 + wn + ((lane & 3) << 1);
    #pragma unroll
    for (int mi = 0; mi < 4; ++mi)
        #pragma unroll
        for (int ni = 0; ni < 8; ++ni) {
            int col = cbase + (ni << 3);
            float b0 = bias_s[col - n0], b1 = bias_s[col - n0 + 1];
            #pragma unroll
            for (int half = 0; half < 2; ++half) {
                int row = rbase + (mi << 4) + (half << 3);
                *reinterpret_cast<float2*>(&outf[(size_t)row * 1024 + col]) =
                    make_float2(acc[mi][ni][half*2] + b0,
                                acc[mi][ni][half*2+1] + b1);
            }
        }
}

// ---------------- tensor-core flash attention --------------------------------
// CTA = 64 q-rows, 128 threads, 2 CTAs/SM, 2-stage pipeline.
// 2q x 2k warp split: warp (qh_i, kh) owns 32 q-rows x 64 k-cols per tile,
// halving per-warp K/V LDSM traffic. Single-term QK (Q pre-scaled, exp2
// domain); fixed-max softmax; l via ones-MMA; partial O/l reduced cross-warp
// through smem at the end.
#define ATT_KV 16384
#define ATT_MB 1024
#define ATT_STAGE (2*ATT_KV + ATT_MB)            // K, V, maskbits = 33792
#define ATT_SMEM (2*ATT_STAGE)                   // 67584

__device__ __forceinline__ void att_stage(
    uint32_t sb, const __half* __restrict__ K, const __half* __restrict__ V,
    const uint32_t* __restrict__ Mb, int kt, int q0, int tid)
{
    #pragma unroll
    for (int i = 0; i < 8; ++i) {
        int seg = tid + (i << 7);
        int row = seg >> 3, cs = seg & 7;
        uint32_t so = row * 128 + ((cs << 4) ^ ((row & 7) << 4));
        size_t gofs = (size_t)((kt << 7) + row) * 64 + (cs << 3);
        cpa16(sb + so,          K + gofs);
        cpa16(sb + ATT_KV + so, V + gofs);
    }
    if (tid < 64)
        cpa16(sb + 2*ATT_KV + tid * 16,
              (const char*)(Mb + (size_t)(q0 + tid) * 64) + (kt << 4));
    CP_COMMIT();
}

__global__ __launch_bounds__(128, 2) void attn_tc()
{
    extern __shared__ __align__(128) char sm[];
    const int tid  = threadIdx.x;
    const int wid  = tid >> 5;
    const int lane = tid & 31;
    const int bh = blockIdx.y;
    const int b = bh >> 4, h = bh & 15;
    const int q0 = blockIdx.x << 6;

    const uint32_t smb = smem_u32(sm);

    const size_t hofs = (size_t)bh * 2048 * 64;
    const __half* gq  = g_q1 + hofs + (size_t)q0 * 64;
    const __half* gk  = g_k1 + hofs;
    const __half* gv  = g_v1 + hofs;
    const uint32_t* gmb = g_mbits + (size_t)b * 2048 * 64;

    // ---- stage Q (single) through buffer 0, extract frags to registers ----
    #pragma unroll
    for (int i = 0; i < 4; ++i) {
        int seg = tid + (i << 7);
        int row = seg >> 3, cs = seg & 7;
        uint32_t so = row * 128 + ((cs << 4) ^ ((row & 7) << 4));
        cpa16(smb + so, gq + (size_t)row * 64 + (cs << 3));
    }
    CP_COMMIT();
    CP_WAIT(0);
    __syncthreads();

    const int lr  = lane & 15;
    const int lxh = (lane >> 4) << 4;
    const int r   = lane >> 2;
    const int c2  = (lane & 3) << 1;
    const int qh_i = wid & 1;          // q half: rows [qh_i*32, +32)
    const int kh   = wid >> 1;         // k half: cols [kh*64, +64) per tile

    uint32_t qf[2][4][4];
    #pragma unroll
    for (int m = 0; m < 2; ++m) {
        int row = (qh_i << 5) + (m << 4) + lr;
        uint32_t rb = smb + row * 128;
        uint32_t sw = (row & 7) << 4;
        #pragma unroll
        for (int kk = 0; kk < 4; ++kk) {
            uint32_t ad = rb + (((kk << 5) + lxh) ^ sw);
            LDSM4(qf[m][kk][0], qf[m][kk][1], qf[m][kk][2], qf[m][kk][3], ad);
        }
    }
    __syncthreads();   // all warps done reading Q before stage 0 overwrite

    att_stage(smb,             gk, gv, gmb, 0, q0, tid);
    att_stage(smb + ATT_STAGE, gk, gv, gmb, 1, q0, tid);

    float o[2][8][4] = {};
    float lacc[2][4] = {};
    const uint32_t ones[2] = {0x3C003C00u, 0x3C003C00u};

    for (int kt = 0; kt < 16; ++kt) {
        if (kt < 15) { CP_WAIT(1); } else { CP_WAIT(0); }
        __syncthreads();
        const uint32_t sb = smb + (kt & 1) * ATT_STAGE;
        const char* stp = sm + (kt & 1) * ATT_STAGE;

        // ---- S = Q x K (single term), warp's 32q x 64k slice ----
        float sc[2][8][4] = {};
        #pragma unroll
        for (int hg = 0; hg < 4; ++hg) {
            int krow = (kh << 6) + (hg << 4) + lr;
            uint32_t rb = sb + krow * 128;
            uint32_t sw = (krow & 7) << 4;
            #pragma unroll
            for (int kk = 0; kk < 4; ++kk) {
                uint32_t ad = rb + (((kk << 5) + lxh) ^ sw);
                uint32_t k0r, k1r, k2r, k3r;
                LDSM4(k0r, k1r, k2r, k3r, ad);
                uint32_t bE[2] = {k0r, k2r}, bO[2] = {k1r, k3r};
                #pragma unroll
                for (int m = 0; m < 2; ++m) {
                    MMA16816(sc[m][2*hg],   qf[m][kk], bE);
                    MMA16816(sc[m][2*hg+1], qf[m][kk], bO);
                }
            }
        }

        // ---- mask bits + fixed-max exp + pack to fp16x2 ----
        uint32_t P[2][16];
        #pragma unroll
        for (int m = 0; m < 2; ++m) {
            int qr = (qh_i << 5) + (m << 4) + r;
            uint2 wA = *reinterpret_cast<const uint2*>(
                stp + 2*ATT_KV + qr * 16 + (kh << 3));
            uint2 wB = *reinterpret_cast<const uint2*>(
                stp + 2*ATT_KV + (qr + 8) * 16 + (kh << 3));
            uint32_t mwA[2] = {wA.x, wA.y};
            uint32_t mwB[2] = {wB.x, wB.y};
            #pragma unroll
            for (int nt = 0; nt < 8; ++nt) {
                uint32_t w0 = mwA[nt >> 2], w1 = mwB[nt >> 2];
                int sh = ((nt & 3) << 3) + c2;
                float e0 = ((w0 >> sh) & 1u)       ? ex2f(sc[m][nt][0]) : 1.0f;
                float e1 = ((w0 >> (sh + 1)) & 1u) ? ex2f(sc[m][nt][1]) : 1.0f;
                float e2 = ((w1 >> sh) & 1u)       ? ex2f(sc[m][nt][2]) : 1.0f;
                float e3 = ((w1 >> (sh + 1)) & 1u) ? ex2f(sc[m][nt][3]) : 1.0f;
                P[m][(nt << 1)]     = pack_h2(e0, e1);
                P[m][(nt << 1) + 1] = pack_h2(e2, e3);
            }
        }

        // ---- l partial on the tensor pipe: lacc += P x ones ----
        #pragma unroll
        for (int m = 0; m < 2; ++m)
            #pragma unroll
            for (int t = 0; t < 4; ++t)
                MMA16816(lacc[m], &P[m][t << 2], ones);

        // ---- O partial += P x V (warp's 64-k slice) ----
        #pragma unroll
        for (int t = 0; t < 4; ++t) {
            int vrow = (kh << 6) + (t << 4) + lr;
            uint32_t rb = sb + ATT_KV + vrow * 128;
            uint32_t sw = (vrow & 7) << 4;
            #pragma unroll
            for (int dp = 0; dp < 4; ++dp) {
                uint32_t ad = rb + (((dp << 5) + lxh) ^ sw);
                uint32_t h0, h1, h2, h3;
                LDSM4T(h0, h1, h2, h3, ad);
                uint32_t bh0[2] = {h0, h1}, bh1[2] = {h2, h3};
                #pragma unroll
                for (int m = 0; m < 2; ++m) {
                    MMA16816(o[m][2*dp],   &P[m][t << 2], bh0);
                    MMA16816(o[m][2*dp+1], &P[m][t << 2], bh1);
                }
            }
        }

        __syncthreads();
        if (kt + 2 < 16)
            att_stage(smb + (kt & 1) * ATT_STAGE, gk, gv, gmb, kt + 2, q0, tid);
    }

    // ---- cross-warp reduction of O/l partials (k-halves), then store ----
    __syncthreads();               // all stage reads done; reuse smem
    float* Opart = reinterpret_cast<float*>(sm);           // 64q x 64d fp32
    float* Lpart = reinterpret_cast<float*>(sm + 16384);   // 64 floats

    if (kh == 1) {
        #pragma unroll
        for (int m = 0; m < 2; ++m) {
            int qrow = (qh_i << 5) + (m << 4) + r;
            #pragma unroll
            for (int ni = 0; ni < 8; ++ni) {
                int d = (ni << 3) + c2;
                Opart[qrow * 64 + d]       = o[m][ni][0];
                Opart[qrow * 64 + d + 1]   = o[m][ni][1];
                Opart[(qrow + 8) * 64 + d]     = o[m][ni][2];
                Opart[(qrow + 8) * 64 + d + 1] = o[m][ni][3];
            }
            Lpart[qrow]     = lacc[m][0];
            Lpart[qrow + 8] = lacc[m][2];
        }
    }
    __syncthreads();
    if (kh == 0) {
        #pragma unroll
        for (int m = 0; m < 2; ++m) {
            int qrow = (qh_i << 5) + (m << 4) + r;
            float i0 = 1.f / (lacc[m][0] + Lpart[qrow]);
            float i1 = 1.f / (lacc[m][2] + Lpart[qrow + 8]);
            int grow = q0 + qrow;
            size_t base0 = ((size_t)(b * 2048) + grow) * 1024 + h * 64;
            size_t base1 = base0 + 8 * 1024;
            #pragma unroll
            for (int ni = 0; ni < 8; ++ni) {
                int d = (ni << 3) + c2;
                float v0 = (o[m][ni][0] + Opart[qrow * 64 + d])       * i0;
                float v1 = (o[m][ni][1] + Opart[qrow * 64 + d + 1])   * i0;
                float v2 = (o[m][ni][2] + Opart[(qrow + 8) * 64 + d])     * i1;
                float v3 = (o[m][ni][3] + Opart[(qrow + 8) * 64 + d + 1]) * i1;
                *reinterpret_cast<uint32_t*>(&g_ao1[base0 + d]) = pack_h2(v0, v1);
                *reinterpret_cast<uint32_t*>(&g_ao1[base1 + d]) = pack_h2(v2, v3);
            }
        }
    }
}

// ---------------------------------------------------------------------------
extern "C" void kernel_launch(void* const* d_in, const int* in_sizes, int n_in,
                              void* d_out, int out_size)
{
    const float* query = (const float*)d_in[0];
    const float* key_  = (const float*)d_in[1];
    const float* value = (const float*)d_in[2];
    const int*   mask  = (const int*)  d_in[3];
    const float* wq = (const float*)d_in[4];
    const float* bq = (const float*)d_in[5];
    const float* wk = (const float*)d_in[6];
    const float* bk = (const float*)d_in[7];
    const float* wv = (const float*)d_in[8];
    const float* bv = (const float*)d_in[9];
    const float* wo = (const float*)d_in[10];
    const float* bo = (const float*)d_in[11];

    void *paq, *pak, *pav, *pwq, *pwk, *pwv, *pwo, *pmb;
    cudaGetSymbolAddress(&paq, g_aq);
    cudaGetSymbolAddress(&pak, g_ak);
    cudaGetSymbolAddress(&pav, g_av);
    cudaGetSymbolAddress(&pwq, g_wq1);
    cudaGetSymbolAddress(&pwk, g_wk1);
    cudaGetSymbolAddress(&pwv, g_wv1);
    cudaGetSymbolAddress(&pwo, g_wo1);
    cudaGetSymbolAddress(&pmb, g_mbits);

    cudaFuncSetAttribute(gemm_qkv,
                         cudaFuncAttributeMaxDynamicSharedMemorySize, G_SMEM);
    cudaFuncSetAttribute(gemm_out,
                         cudaFuncAttributeMaxDynamicSharedMemorySize, G_SMEM);
    cudaFuncSetAttribute(attn_tc,
                         cudaFuncAttributeMaxDynamicSharedMemorySize, ATT_SMEM);

    conv_maskbits<<<65536, 256>>>(mask, (uint32_t*)pmb);
    conv_h1x3<<<dim3(8192, 3), 256>>>(
        (const float4*)query, (const float4*)key_, (const float4*)value,
        (uint2*)paq, (uint2*)pak, (uint2*)pav);
    conv_h1x4<<<dim3(1024, 4), 256>>>(
        (const float4*)wq, (const float4*)wk, (const float4*)wv,
        (const float4*)wo,
        (uint2*)pwq, (uint2*)pwk, (uint2*)pwv, (uint2*)pwo);

    gemm_qkv<<<dim3(8, 64, 3), 128, G_SMEM>>>(bq, bk, bv);
    attn_tc<<<dim3(32, 64), 128, ATT_SMEM>>>();
    gemm_out<<<dim3(8, 64), 128, G_SMEM>>>(bo, (float*)d_out);
}

// round 14
// speedup vs baseline: 1.4488x; 1.1938x over previous
#include <cuda_runtime.h>
#include <cuda_fp16.h>
#include <cstdint>

// ---------------- scratch (__device__ globals; no allocs allowed) -----------
__device__ __half g_aq[8192*1024];             // fp16 A inputs (single)
__device__ __half g_ak[8192*1024];
__device__ __half g_av[8192*1024];
__device__ __half g_ao1[8192*1024];            // attention out (single fp16)
__device__ __half g_wq1[1024*1024];            // weights single fp16
__device__ __half g_wk1[1024*1024];
__device__ __half g_wv1[1024*1024];
__device__ __half g_wo1[1024*1024];
__device__ __half g_q1 [4*16*2048*64];         // Q single (pre-scaled 0.125*log2e)
__device__ __half g_k1 [4*16*2048*64];         // K single
__device__ __half g_v1 [4*16*2048*64];         // V single
__device__ uint32_t g_mbits[4*2048*64];        // bit mask: 64 words per row

// ---------------- PTX helpers (generic ISA, valid at compute_103) -----------
__device__ __forceinline__ uint32_t smem_u32(const void* p) {
    uint32_t a;
    asm("{ .reg .u64 t; cvta.to.shared.u64 t, %1; cvt.u32.u64 %0, t; }"
        : "=r"(a) : "l"(p));
    return a;
}
__device__ __forceinline__ void cpa16(uint32_t dst, const void* src) {
    asm volatile("cp.async.cg.shared.global [%0], [%1], 16;"
                 :: "r"(dst), "l"(src) : "memory");
}
#define CP_COMMIT() asm volatile("cp.async.commit_group;" ::: "memory")
#define CP_WAIT(n)  asm volatile("cp.async.wait_group %0;" :: "n"(n) : "memory")

#define LDSM4(r0, r1, r2, r3, addr)                                          \
    asm volatile("ldmatrix.sync.aligned.m8n8.x4.shared.b16 {%0,%1,%2,%3}, [%4];" \
                 : "=r"(r0), "=r"(r1), "=r"(r2), "=r"(r3) : "r"(addr))
#define LDSM4T(r0, r1, r2, r3, addr)                                         \
    asm volatile("ldmatrix.sync.aligned.m8n8.x4.trans.shared.b16 {%0,%1,%2,%3}, [%4];" \
                 : "=r"(r0), "=r"(r1), "=r"(r2), "=r"(r3) : "r"(addr))

#define MMA16816(d, a, b)                                                    \
    asm volatile("mma.sync.aligned.m16n8k16.row.col.f32.f16.f16.f32 "        \
                 "{%0,%1,%2,%3}, {%4,%5,%6,%7}, {%8,%9}, {%0,%1,%2,%3};"     \
                 : "+f"((d)[0]), "+f"((d)[1]), "+f"((d)[2]), "+f"((d)[3])    \
                 : "r"((a)[0]), "r"((a)[1]), "r"((a)[2]), "r"((a)[3]),       \
                   "r"((b)[0]), "r"((b)[1]))

__device__ __forceinline__ uint32_t pack_h2(float a, float b) {
    __half2 h = __floats2half2_rn(a, b);
    return *reinterpret_cast<uint32_t*>(&h);
}
__device__ __forceinline__ uint32_t ex2_h2(uint32_t h2) {
    uint32_t r;
    asm("ex2.approx.f16x2 %0, %1;" : "=r"(r) : "r"(h2));
    return r;
}

// ---------------- conversions (fused launches) -------------------------------
__global__ __launch_bounds__(256) void conv_h1x3(
    const float4* __restrict__ s0, const float4* __restrict__ s1,
    const float4* __restrict__ s2, uint2* __restrict__ d0,
    uint2* __restrict__ d1, uint2* __restrict__ d2)
{
    int z = blockIdx.y;
    const float4* src = (z == 0) ? s0 : (z == 1) ? s1 : s2;
    uint2* dst = (z == 0) ? d0 : (z == 1) ? d1 : d2;
    int i = blockIdx.x * blockDim.x + threadIdx.x;
    float4 v = src[i];
    dst[i] = make_uint2(pack_h2(v.x, v.y), pack_h2(v.z, v.w));
}

__global__ __launch_bounds__(256) void conv_h1x4(
    const float4* __restrict__ s0, const float4* __restrict__ s1,
    const float4* __restrict__ s2, const float4* __restrict__ s3,
    uint2* __restrict__ d0, uint2* __restrict__ d1,
    uint2* __restrict__ d2, uint2* __restrict__ d3)
{
    int z = blockIdx.y;
    const float4* src = (z == 0) ? s0 : (z == 1) ? s1 : (z == 2) ? s2 : s3;
    uint2* dst = (z == 0) ? d0 : (z == 1) ? d1 : (z == 2) ? d2 : d3;
    int i = blockIdx.x * blockDim.x + threadIdx.x;
    float4 v = src[i];
    dst[i] = make_uint2(pack_h2(v.x, v.y), pack_h2(v.z, v.w));
}

__global__ __launch_bounds__(256) void conv_maskbits(
    const int* __restrict__ src, uint32_t* __restrict__ dst)
{
    int gw = (blockIdx.x * blockDim.x + threadIdx.x) >> 5;
    int lane = threadIdx.x & 31;
    int v = src[(size_t)gw * 32 + lane];
    uint32_t b = __ballot_sync(0xffffffffu, v != 0);
    if (lane == 0) dst[gw] = b;
}

// ---------------- fp16 single-term GEMM core (mma.sync) ---------------------
// C = A(fp16) @ W(fp16)^T. CTA 128x128, BK=64, 3-stage cp.async, 2 CTAs/SM.
#define G_MAT 16384
#define G_STAGE (2 * G_MAT)                  // A, W = 32768
#define G_SMEM (3 * G_STAGE)                 // 98304

__device__ __forceinline__ void g_stage2(
    uint32_t sb, const __half* __restrict__ pA, const __half* __restrict__ pW,
    int kt, int tid)
{
    const __half* srcs[2] = {pA, pW};
    #pragma unroll
    for (int m = 0; m < 2; ++m) {
        uint32_t mb = sb + m * G_MAT;
        const __half* sp = srcs[m];
        #pragma unroll
        for (int i = 0; i < 8; ++i) {
            int seg = tid + (i << 7);
            int row = seg >> 3, cs = seg & 7;
            cpa16(mb + row * 128 + ((cs << 4) ^ ((row & 7) << 4)),
                  sp + (size_t)row * 1024 + (kt << 6) + (cs << 3));
        }
    }
    CP_COMMIT();
}

#define GLOAD(buf, kk, sb)                                                   \
    do {                                                                     \
        const int x_ = ((kk) << 5) + lxh;                                    \
        _Pragma("unroll")                                                    \
        for (int mi = 0; mi < 4; ++mi) {                                     \
            int row = wm + (mi << 4) + lr;                                   \
            uint32_t ad = (sb) + row * 128 + (x_ ^ ((row & 7) << 4));        \
            LDSM4(af[buf][mi][0], af[buf][mi][1], af[buf][mi][2],            \
                  af[buf][mi][3], ad);                                       \
        }                                                                    \
        _Pragma("unroll")                                                    \
        for (int g = 0; g < 4; ++g) {                                        \
            int row = wn + (g << 4) + lr;                                    \
            uint32_t wd = (sb) + G_MAT + row * 128 + (x_ ^ ((row & 7) << 4));\
            uint32_t r0, r1, r2, r3;                                         \
            LDSM4(r0, r1, r2, r3, wd);                                       \
            wf[buf][2*g][0] = r0; wf[buf][2*g][1] = r2;                      \
            wf[buf][2*g+1][0] = r1; wf[buf][2*g+1][1] = r3;                  \
        }                                                                    \
    } while (0)

#define GEMM_BODY(pA, pW)                                                    \
    g_stage2(sb0,           (pA), (pW), 0, tid);                             \
    g_stage2(sb0 + G_STAGE, (pA), (pW), 1, tid);                             \
    uint32_t af[2][4][4], wf[2][8][2];                                       \
    for (int j = 0; j < 16; ++j) {                                           \
        if (j < 15) { CP_WAIT(1); } else { CP_WAIT(0); }                     \
        __syncthreads();                                                     \
        if (j + 2 < 16)                                                      \
            g_stage2(sb0 + ((j + 2) % 3) * G_STAGE, (pA), (pW), j + 2, tid); \
        const uint32_t sb = sb0 + (j % 3) * G_STAGE;                         \
        GLOAD(0, 0, sb);                                                     \
        _Pragma("unroll")                                                    \
        for (int kk = 0; kk < 4; ++kk) {                                     \
            if (kk < 3) GLOAD((kk + 1) & 1, kk + 1, sb);                     \
            const int cb = kk & 1;                                           \
            _Pragma("unroll")                                                \
            for (int mi = 0; mi < 4; ++mi)                                   \
                _Pragma("unroll")                                            \
                for (int ni = 0; ni < 8; ++ni)                               \
                    MMA16816(acc[mi][ni], af[cb][mi], wf[cb][ni]);           \
        }                                                                    \
    }

__global__ __launch_bounds__(128, 2) void gemm_qkv(
    const float* __restrict__ bq, const float* __restrict__ bk,
    const float* __restrict__ bv)
{
    extern __shared__ __align__(128) char dynsm[];
    __shared__ float bias_s[128];

    const int tid  = threadIdx.x;
    const int wid  = tid >> 5;
    const int lane = tid & 31;
    const int m0 = blockIdx.y << 7;
    const int n0 = blockIdx.x << 7;
    const int z  = blockIdx.z;
    const int wm = (wid >> 1) << 6;     // 0 or 64
    const int wn = (wid & 1) << 6;      // 0 or 64
    const int lr = lane & 15;
    const int lxh = (lane >> 4) << 4;

    const __half* A = (z == 0) ? g_aq  : (z == 1) ? g_ak  : g_av;
    const __half* W = (z == 0) ? g_wq1 : (z == 1) ? g_wk1 : g_wv1;
    const float* bias = (z == 0) ? bq : (z == 1) ? bk : bv;

    bias_s[tid] = bias[n0 + tid];

    const uint32_t sb0 = smem_u32(dynsm);
    const __half* pA = A + (size_t)m0 * 1024;
    const __half* pW = W + (size_t)n0 * 1024;

    float acc[4][8][4] = {};
    GEMM_BODY(pA, pW)

    // epilogue: scatter [B,H,S,dk]; z=0 Q (pre-scaled 0.125*log2e), z=1 K, z=2 V
    const int rbase = m0 + wm + (lane >> 2);
    const int cbase = n0 + wn + ((lane & 3) << 1);
    #pragma unroll
    for (int mi = 0; mi < 4; ++mi) {
        #pragma unroll
        for (int ni = 0; ni < 8; ++ni) {
            int col = cbase + (ni << 3);
            float b0 = bias_s[col - n0], b1 = bias_s[col - n0 + 1];
            #pragma unroll
            for (int half = 0; half < 2; ++half) {
                int row = rbase + (mi << 4) + (half << 3);
                float v0 = acc[mi][ni][half*2]   + b0;
                float v1 = acc[mi][ni][half*2+1] + b1;
                int h = col >> 6, d = col & 63;
                int bb = row >> 11, s = row & 2047;
                size_t idx = ((size_t)((bb << 4) + h) * 2048 + s) * 64 + d;
                if (z == 0) {
                    v0 *= 0.18033688f; v1 *= 0.18033688f;   // 0.125 * log2(e)
                    *reinterpret_cast<uint32_t*>(&g_q1[idx]) = pack_h2(v0, v1);
                } else if (z == 1) {
                    *reinterpret_cast<uint32_t*>(&g_k1[idx]) = pack_h2(v0, v1);
                } else {
                    *reinterpret_cast<uint32_t*>(&g_v1[idx]) = pack_h2(v0, v1);
                }
            }
        }
    }
}

__global__ __launch_bounds__(128, 2) void gemm_out(
    const float* __restrict__ bo, float* __restrict__ outf)
{
    extern __shared__ __align__(128) char dynsm[];
    __shared__ float bias_s[128];

    const int tid  = threadIdx.x;
    const int wid  = tid >> 5;
    const int lane = tid & 31;
    const int m0 = blockIdx.y << 7;
    const int n0 = blockIdx.x << 7;
    const int wm = (wid >> 1) << 6;
    const int wn = (wid & 1) << 6;
    const int lr = lane & 15;
    const int lxh = (lane >> 4) << 4;

    bias_s[tid] = bo[n0 + tid];

    const uint32_t sb0 = smem_u32(dynsm);
    const __half* pA = g_ao1 + (size_t)m0 * 1024;
    const __half* pW = g_wo1 + (size_t)n0 * 1024;

    float acc[4][8][4] = {};
    GEMM_BODY(pA, pW)

    const int rbase = m0 + wm + (lane >> 2);
    const int cbase = n0 + wn + ((lane & 3) << 1);
    #pragma unroll
    for (int mi = 0; mi < 4; ++mi)
        #pragma unroll
        for (int ni = 0; ni < 8; ++ni) {
            int col = cbase + (ni << 3);
            float b0 = bias_s[col - n0], b1 = bias_s[col - n0 + 1];
            #pragma unroll
            for (int half = 0; half < 2; ++half) {
                int row = rbase + (mi << 4) + (half << 3);
                *reinterpret_cast<float2*>(&outf[(size_t)row * 1024 + col]) =
                    make_float2(acc[mi][ni][half*2] + b0,
                                acc[mi][ni][half*2+1] + b1);
            }
        }
}

// ---------------- tensor-core flash attention --------------------------------
// CTA = 64 q-rows, 128 threads, 2 CTAs/SM, 2-stage pipeline, 2q x 2k warp
// split. Single-term QK (Q pre-scaled, exp2 domain). Softmax: masked scores
// forced to 0.0 (exp2(0)=1), pack fp32 pair -> fp16x2, ONE ex2.approx.f16x2
// per pair (halves MUFU, output is already the P fragment). l via ones-MMA.
#define ATT_KV 16384
#define ATT_MB 1024
#define ATT_STAGE (2*ATT_KV + ATT_MB)            // K, V, maskbits = 33792
#define ATT_SMEM (2*ATT_STAGE)                   // 67584

__device__ __forceinline__ void att_stage(
    uint32_t sb, const __half* __restrict__ K, const __half* __restrict__ V,
    const uint32_t* __restrict__ Mb, int kt, int q0, int tid)
{
    #pragma unroll
    for (int i = 0; i < 8; ++i) {
        int seg = tid + (i << 7);
        int row = seg >> 3, cs = seg & 7;
        uint32_t so = row * 128 + ((cs << 4) ^ ((row & 7) << 4));
        size_t gofs = (size_t)((kt << 7) + row) * 64 + (cs << 3);
        cpa16(sb + so,          K + gofs);
        cpa16(sb + ATT_KV + so, V + gofs);
    }
    if (tid < 64)
        cpa16(sb + 2*ATT_KV + tid * 16,
              (const char*)(Mb + (size_t)(q0 + tid) * 64) + (kt << 4));
    CP_COMMIT();
}

__global__ __launch_bounds__(128, 2) void attn_tc()
{
    extern __shared__ __align__(128) char sm[];
    const int tid  = threadIdx.x;
    const int wid  = tid >> 5;
    const int lane = tid & 31;
    const int bh = blockIdx.y;
    const int b = bh >> 4, h = bh & 15;
    const int q0 = blockIdx.x << 6;

    const uint32_t smb = smem_u32(sm);

    const size_t hofs = (size_t)bh * 2048 * 64;
    const __half* gq  = g_q1 + hofs + (size_t)q0 * 64;
    const __half* gk  = g_k1 + hofs;
    const __half* gv  = g_v1 + hofs;
    const uint32_t* gmb = g_mbits + (size_t)b * 2048 * 64;

    // ---- stage Q (single) through buffer 0, extract frags to registers ----
    #pragma unroll
    for (int i = 0; i < 4; ++i) {
        int seg = tid + (i << 7);
        int row = seg >> 3, cs = seg & 7;
        uint32_t so = row * 128 + ((cs << 4) ^ ((row & 7) << 4));
        cpa16(smb + so, gq + (size_t)row * 64 + (cs << 3));
    }
    CP_COMMIT();
    CP_WAIT(0);
    __syncthreads();

    const int lr  = lane & 15;
    const int lxh = (lane >> 4) << 4;
    const int r   = lane >> 2;
    const int c2  = (lane & 3) << 1;
    const int qh_i = wid & 1;          // q half: rows [qh_i*32, +32)
    const int kh   = wid >> 1;         // k half: cols [kh*64, +64) per tile

    uint32_t qf[2][4][4];
    #pragma unroll
    for (int m = 0; m < 2; ++m) {
        int row = (qh_i << 5) + (m << 4) + lr;
        uint32_t rb = smb + row * 128;
        uint32_t sw = (row & 7) << 4;
        #pragma unroll
        for (int kk = 0; kk < 4; ++kk) {
            uint32_t ad = rb + (((kk << 5) + lxh) ^ sw);
            LDSM4(qf[m][kk][0], qf[m][kk][1], qf[m][kk][2], qf[m][kk][3], ad);
        }
    }
    __syncthreads();   // all warps done reading Q before stage 0 overwrite

    att_stage(smb,             gk, gv, gmb, 0, q0, tid);
    att_stage(smb + ATT_STAGE, gk, gv, gmb, 1, q0, tid);

    float o[2][8][4] = {};
    float lacc[2][4] = {};
    const uint32_t ones[2] = {0x3C003C00u, 0x3C003C00u};

    for (int kt = 0; kt < 16; ++kt) {
        if (kt < 15) { CP_WAIT(1); } else { CP_WAIT(0); }
        __syncthreads();
        const uint32_t sb = smb + (kt & 1) * ATT_STAGE;
        const char* stp = sm + (kt & 1) * ATT_STAGE;

        // ---- S = Q x K (single term), warp's 32q x 64k slice ----
        float sc[2][8][4] = {};
        #pragma unroll
        for (int hg = 0; hg < 4; ++hg) {
            int krow = (kh << 6) + (hg << 4) + lr;
            uint32_t rb = sb + krow * 128;
            uint32_t sw = (krow & 7) << 4;
            #pragma unroll
            for (int kk = 0; kk < 4; ++kk) {
                uint32_t ad = rb + (((kk << 5) + lxh) ^ sw);
                uint32_t k0r, k1r, k2r, k3r;
                LDSM4(k0r, k1r, k2r, k3r, ad);
                uint32_t bE[2] = {k0r, k2r}, bO[2] = {k1r, k3r};
                #pragma unroll
                for (int m = 0; m < 2; ++m) {
                    MMA16816(sc[m][2*hg],   qf[m][kk], bE);
                    MMA16816(sc[m][2*hg+1], qf[m][kk], bO);
                }
            }
        }

        // ---- mask -> score 0 (exp2(0)=1), pack fp16x2, ex2.f16x2 -> P ----
        uint32_t P[2][16];
        #pragma unroll
        for (int m = 0; m < 2; ++m) {
            int qr = (qh_i << 5) + (m << 4) + r;
            uint2 wA = *reinterpret_cast<const uint2*>(
                stp + 2*ATT_KV + qr * 16 + (kh << 3));
            uint2 wB = *reinterpret_cast<const uint2*>(
                stp + 2*ATT_KV + (qr + 8) * 16 + (kh << 3));
            uint32_t mwA[2] = {wA.x, wA.y};
            uint32_t mwB[2] = {wB.x, wB.y};
            #pragma unroll
            for (int nt = 0; nt < 8; ++nt) {
                uint32_t w0 = mwA[nt >> 2], w1 = mwB[nt >> 2];
                int sh = ((nt & 3) << 3) + c2;
                float s0 = ((w0 >> sh) & 1u)       ? sc[m][nt][0] : 0.0f;
                float s1 = ((w0 >> (sh + 1)) & 1u) ? sc[m][nt][1] : 0.0f;
                float s2 = ((w1 >> sh) & 1u)       ? sc[m][nt][2] : 0.0f;
                float s3 = ((w1 >> (sh + 1)) & 1u) ? sc[m][nt][3] : 0.0f;
                P[m][(nt << 1)]     = ex2_h2(pack_h2(s0, s1));
                P[m][(nt << 1) + 1] = ex2_h2(pack_h2(s2, s3));
            }
        }

        // ---- l partial on the tensor pipe: lacc += P x ones ----
        #pragma unroll
        for (int m = 0; m < 2; ++m)
            #pragma unroll
            for (int t = 0; t < 4; ++t)
                MMA16816(lacc[m], &P[m][t << 2], ones);

        // ---- O partial += P x V (warp's 64-k slice) ----
        #pragma unroll
        for (int t = 0; t < 4; ++t) {
            int vrow = (kh << 6) + (t << 4) + lr;
            uint32_t rb = sb + ATT_KV + vrow * 128;
            uint32_t sw = (vrow & 7) << 4;
            #pragma unroll
            for (int dp = 0; dp < 4; ++dp) {
                uint32_t ad = rb + (((dp << 5) + lxh) ^ sw);
                uint32_t h0, h1, h2, h3;
                LDSM4T(h0, h1, h2, h3, ad);
                uint32_t bh0[2] = {h0, h1}, bh1[2] = {h2, h3};
                #pragma unroll
                for (int m = 0; m < 2; ++m) {
                    MMA16816(o[m][2*dp],   &P[m][t << 2], bh0);
                    MMA16816(o[m][2*dp+1], &P[m][t << 2], bh1);
                }
            }
        }

        __syncthreads();
        if (kt + 2 < 16)
            att_stage(smb + (kt & 1) * ATT_STAGE, gk, gv, gmb, kt + 2, q0, tid);
    }

    // ---- cross-warp reduction of O/l partials (k-halves), then store ----
    __syncthreads();               // all stage reads done; reuse smem
    float* Opart = reinterpret_cast<float*>(sm);           // 64q x 64d fp32
    float* Lpart = reinterpret_cast<float*>(sm + 16384);   // 64 floats

    if (kh == 1) {
        #pragma unroll
        for (int m = 0; m < 2; ++m) {
            int qrow = (qh_i << 5) + (m << 4) + r;
            #pragma unroll
            for (int ni = 0; ni < 8; ++ni) {
                int d = (ni << 3) + c2;
                Opart[qrow * 64 + d]       = o[m][ni][0];
                Opart[qrow * 64 + d + 1]   = o[m][ni][1];
                Opart[(qrow + 8) * 64 + d]     = o[m][ni][2];
                Opart[(qrow + 8) * 64 + d + 1] = o[m][ni][3];
            }
            Lpart[qrow]     = lacc[m][0];
            Lpart[qrow + 8] = lacc[m][2];
        }
    }
    __syncthreads();
    if (kh == 0) {
        #pragma unroll
        for (int m = 0; m < 2; ++m) {
            int qrow = (qh_i << 5) + (m << 4) + r;
            float i0 = 1.f / (lacc[m][0] + Lpart[qrow]);
            float i1 = 1.f / (lacc[m][2] + Lpart[qrow + 8]);
            int grow = q0 + qrow;
            size_t base0 = ((size_t)(b * 2048) + grow) * 1024 + h * 64;
            size_t base1 = base0 + 8 * 1024;
            #pragma unroll
            for (int ni = 0; ni < 8; ++ni) {
                int d = (ni << 3) + c2;
                float v0 = (o[m][ni][0] + Opart[qrow * 64 + d])       * i0;
                float v1 = (o[m][ni][1] + Opart[qrow * 64 + d + 1])   * i0;
                float v2 = (o[m][ni][2] + Opart[(qrow + 8) * 64 + d])     * i1;
                float v3 = (o[m][ni][3] + Opart[(qrow + 8) * 64 + d + 1]) * i1;
                *reinterpret_cast<uint32_t*>(&g_ao1[base0 + d]) = pack_h2(v0, v1);
                *reinterpret_cast<uint32_t*>(&g_ao1[base1 + d]) = pack_h2(v2, v3);
            }
        }
    }
}

// ---------------------------------------------------------------------------
extern "C" void kernel_launch(void* const* d_in, const int* in_sizes, int n_in,
                              void* d_out, int out_size)
{
    const float* query = (const float*)d_in[0];
    const float* key_  = (const float*)d_in[1];
    const float* value = (const float*)d_in[2];
    const int*   mask  = (const int*)  d_in[3];
    const float* wq = (const float*)d_in[4];
    const float* bq = (const float*)d_in[5];
    const float* wk = (const float*)d_in[6];
    const float* bk = (const float*)d_in[7];
    const float* wv = (const float*)d_in[8];
    const float* bv = (const float*)d_in[9];
    const float* wo = (const float*)d_in[10];
    const float* bo = (const float*)d_in[11];

    void *paq, *pak, *pav, *pwq, *pwk, *pwv, *pwo, *pmb;
    cudaGetSymbolAddress(&paq, g_aq);
    cudaGetSymbolAddress(&pak, g_ak);
    cudaGetSymbolAddress(&pav, g_av);
    cudaGetSymbolAddress(&pwq, g_wq1);
    cudaGetSymbolAddress(&pwk, g_wk1);
    cudaGetSymbolAddress(&pwv, g_wv1);
    cudaGetSymbolAddress(&pwo, g_wo1);
    cudaGetSymbolAddress(&pmb, g_mbits);

    cudaFuncSetAttribute(gemm_qkv,
                         cudaFuncAttributeMaxDynamicSharedMemorySize, G_SMEM);
    cudaFuncSetAttribute(gemm_out,
                         cudaFuncAttributeMaxDynamicSharedMemorySize, G_SMEM);
    cudaFuncSetAttribute(attn_tc,
                         cudaFuncAttributeMaxDynamicSharedMemorySize, ATT_SMEM);

    conv_maskbits<<<65536, 256>>>(mask, (uint32_t*)pmb);
    conv_h1x3<<<dim3(8192, 3), 256>>>(
        (const float4*)query, (const float4*)key_, (const float4*)value,
        (uint2*)paq, (uint2*)pak, (uint2*)pav);
    conv_h1x4<<<dim3(1024, 4), 256>>>(
        (const float4*)wq, (const float4*)wk, (const float4*)wv,
        (const float4*)wo,
        (uint2*)pwq, (uint2*)pwk, (uint2*)pwv, (uint2*)pwo);

    gemm_qkv<<<dim3(8, 64, 3), 128, G_SMEM>>>(bq, bk, bv);
    attn_tc<<<dim3(32, 64), 128, ATT_SMEM>>>();
    gemm_out<<<dim3(8, 64), 128, G_SMEM>>>(bo, (float*)d_out);
}

// round 15
// speedup vs baseline: 1.4827x; 1.0234x over previous
#include <cuda_runtime.h>
#include <cuda_fp16.h>
#include <cstdint>

// ---------------- scratch (__device__ globals; no allocs allowed) -----------
__device__ __half g_aq[8192*1024];             // fp16 A inputs (single)
__device__ __half g_ak[8192*1024];
__device__ __half g_av[8192*1024];
__device__ __half g_ao1[8192*1024];            // attention out (single fp16)
__device__ __half g_wq1[1024*1024];            // weights single fp16
__device__ __half g_wk1[1024*1024];
__device__ __half g_wv1[1024*1024];
__device__ __half g_wo1[1024*1024];
__device__ __half g_q1 [4*16*2048*64];         // Q single (pre-scaled 0.125*log2e)
__device__ __half g_k1 [4*16*2048*64];         // K single
__device__ __half g_v1 [4*16*2048*64];         // V single
__device__ uint32_t g_mbits[4*2048*64];        // bit mask: 64 words per row

// ---------------- PTX helpers (generic ISA, valid at compute_103) -----------
__device__ __forceinline__ uint32_t smem_u32(const void* p) {
    uint32_t a;
    asm("{ .reg .u64 t; cvta.to.shared.u64 t, %1; cvt.u32.u64 %0, t; }"
        : "=r"(a) : "l"(p));
    return a;
}
__device__ __forceinline__ void cpa16(uint32_t dst, const void* src) {
    asm volatile("cp.async.cg.shared.global [%0], [%1], 16;"
                 :: "r"(dst), "l"(src) : "memory");
}
#define CP_COMMIT() asm volatile("cp.async.commit_group;" ::: "memory")
#define CP_WAIT(n)  asm volatile("cp.async.wait_group %0;" :: "n"(n) : "memory")

#define LDSM4(r0, r1, r2, r3, addr)                                          \
    asm volatile("ldmatrix.sync.aligned.m8n8.x4.shared.b16 {%0,%1,%2,%3}, [%4];" \
                 : "=r"(r0), "=r"(r1), "=r"(r2), "=r"(r3) : "r"(addr))
#define LDSM4T(r0, r1, r2, r3, addr)                                         \
    asm volatile("ldmatrix.sync.aligned.m8n8.x4.trans.shared.b16 {%0,%1,%2,%3}, [%4];" \
                 : "=r"(r0), "=r"(r1), "=r"(r2), "=r"(r3) : "r"(addr))

#define MMA16816(d, a, b)                                                    \
    asm volatile("mma.sync.aligned.m16n8k16.row.col.f32.f16.f16.f32 "        \
                 "{%0,%1,%2,%3}, {%4,%5,%6,%7}, {%8,%9}, {%0,%1,%2,%3};"     \
                 : "+f"((d)[0]), "+f"((d)[1]), "+f"((d)[2]), "+f"((d)[3])    \
                 : "r"((a)[0]), "r"((a)[1]), "r"((a)[2]), "r"((a)[3]),       \
                   "r"((b)[0]), "r"((b)[1]))

__device__ __forceinline__ uint32_t pack_h2(float a, float b) {
    __half2 h = __floats2half2_rn(a, b);
    return *reinterpret_cast<uint32_t*>(&h);
}
__device__ __forceinline__ uint32_t ex2_h2(uint32_t h2) {
    uint32_t r;
    asm("ex2.approx.f16x2 %0, %1;" : "=r"(r) : "r"(h2));
    return r;
}

// ---------------- conversions (fused launches, 4x ILP) -----------------------
__global__ __launch_bounds__(256) void conv_h1x3(
    const float4* __restrict__ s0, const float4* __restrict__ s1,
    const float4* __restrict__ s2, uint2* __restrict__ d0,
    uint2* __restrict__ d1, uint2* __restrict__ d2)
{
    int z = blockIdx.y;
    const float4* src = (z == 0) ? s0 : (z == 1) ? s1 : s2;
    uint2* dst = (z == 0) ? d0 : (z == 1) ? d1 : d2;
    int i = (blockIdx.x * blockDim.x + threadIdx.x) << 2;
    float4 v0 = src[i], v1 = src[i+1], v2 = src[i+2], v3 = src[i+3];
    dst[i]   = make_uint2(pack_h2(v0.x, v0.y), pack_h2(v0.z, v0.w));
    dst[i+1] = make_uint2(pack_h2(v1.x, v1.y), pack_h2(v1.z, v1.w));
    dst[i+2] = make_uint2(pack_h2(v2.x, v2.y), pack_h2(v2.z, v2.w));
    dst[i+3] = make_uint2(pack_h2(v3.x, v3.y), pack_h2(v3.z, v3.w));
}

__global__ __launch_bounds__(256) void conv_h1x4(
    const float4* __restrict__ s0, const float4* __restrict__ s1,
    const float4* __restrict__ s2, const float4* __restrict__ s3,
    uint2* __restrict__ d0, uint2* __restrict__ d1,
    uint2* __restrict__ d2, uint2* __restrict__ d3)
{
    int z = blockIdx.y;
    const float4* src = (z == 0) ? s0 : (z == 1) ? s1 : (z == 2) ? s2 : s3;
    uint2* dst = (z == 0) ? d0 : (z == 1) ? d1 : (z == 2) ? d2 : d3;
    int i = (blockIdx.x * blockDim.x + threadIdx.x) << 2;
    float4 v0 = src[i], v1 = src[i+1], v2 = src[i+2], v3 = src[i+3];
    dst[i]   = make_uint2(pack_h2(v0.x, v0.y), pack_h2(v0.z, v0.w));
    dst[i+1] = make_uint2(pack_h2(v1.x, v1.y), pack_h2(v1.z, v1.w));
    dst[i+2] = make_uint2(pack_h2(v2.x, v2.y), pack_h2(v2.z, v2.w));
    dst[i+3] = make_uint2(pack_h2(v3.x, v3.y), pack_h2(v3.z, v3.w));
}

__global__ __launch_bounds__(256) void conv_maskbits(
    const int4* __restrict__ src4, uint32_t* __restrict__ dst)
{
    int warp = (blockIdx.x * blockDim.x + threadIdx.x) >> 5;
    int lane = threadIdx.x & 31;
    int4 v = src4[(size_t)warp * 32 + lane];
    uint32_t nib = (v.x != 0 ? 1u : 0u) | (v.y != 0 ? 2u : 0u) |
                   (v.z != 0 ? 4u : 0u) | (v.w != 0 ? 8u : 0u);
    uint32_t word = nib << ((lane & 7) << 2);
    word |= __shfl_xor_sync(~0u, word, 1);
    word |= __shfl_xor_sync(~0u, word, 2);
    word |= __shfl_xor_sync(~0u, word, 4);
    if ((lane & 7) == 0) dst[(size_t)warp * 4 + (lane >> 3)] = word;
}

// ---------------- fp16 single-term GEMM core (mma.sync) ---------------------
// C = A(fp16) @ W(fp16)^T. CTA 128x128, BK=64, 3-stage cp.async, 2 CTAs/SM.
#define G_MAT 16384
#define G_STAGE (2 * G_MAT)                  // A, W = 32768
#define G_SMEM (3 * G_STAGE)                 // 98304

__device__ __forceinline__ void g_stage2(
    uint32_t sb, const __half* __restrict__ pA, const __half* __restrict__ pW,
    int kt, int tid)
{
    const __half* srcs[2] = {pA, pW};
    #pragma unroll
    for (int m = 0; m < 2; ++m) {
        uint32_t mb = sb + m * G_MAT;
        const __half* sp = srcs[m];
        #pragma unroll
        for (int i = 0; i < 8; ++i) {
            int seg = tid + (i << 7);
            int row = seg >> 3, cs = seg & 7;
            cpa16(mb + row * 128 + ((cs << 4) ^ ((row & 7) << 4)),
                  sp + (size_t)row * 1024 + (kt << 6) + (cs << 3));
        }
    }
    CP_COMMIT();
}

#define GLOAD(buf, kk, sb)                                                   \
    do {                                                                     \
        const int x_ = ((kk) << 5) + lxh;                                    \
        _Pragma("unroll")                                                    \
        for (int mi = 0; mi < 4; ++mi) {                                     \
            int row = wm + (mi << 4) + lr;                                   \
            uint32_t ad = (sb) + row * 128 + (x_ ^ ((row & 7) << 4));        \
            LDSM4(af[buf][mi][0], af[buf][mi][1], af[buf][mi][2],            \
                  af[buf][mi][3], ad);                                       \
        }                                                                    \
        _Pragma("unroll")                                                    \
        for (int g = 0; g < 4; ++g) {                                        \
            int row = wn + (g << 4) + lr;                                    \
            uint32_t wd = (sb) + G_MAT + row * 128 + (x_ ^ ((row & 7) << 4));\
            uint32_t r0, r1, r2, r3;                                         \
            LDSM4(r0, r1, r2, r3, wd);                                       \
            wf[buf][2*g][0] = r0; wf[buf][2*g][1] = r2;                      \
            wf[buf][2*g+1][0] = r1; wf[buf][2*g+1][1] = r3;                  \
        }                                                                    \
    } while (0)

#define GEMM_BODY(pA, pW)                                                    \
    g_stage2(sb0,           (pA), (pW), 0, tid);                             \
    g_stage2(sb0 + G_STAGE, (pA), (pW), 1, tid);                             \
    uint32_t af[2][4][4], wf[2][8][2];                                       \
    for (int j = 0; j < 16; ++j) {                                           \
        if (j < 15) { CP_WAIT(1); } else { CP_WAIT(0); }                     \
        __syncthreads();                                                     \
        if (j + 2 < 16)                                                      \
            g_stage2(sb0 + ((j + 2) % 3) * G_STAGE, (pA), (pW), j + 2, tid); \
        const uint32_t sb = sb0 + (j % 3) * G_STAGE;                         \
        GLOAD(0, 0, sb);                                                     \
        _Pragma("unroll")                                                    \
        for (int kk = 0; kk < 4; ++kk) {                                     \
            if (kk < 3) GLOAD((kk + 1) & 1, kk + 1, sb);                     \
            const int cb = kk & 1;                                           \
            _Pragma("unroll")                                                \
            for (int mi = 0; mi < 4; ++mi)                                   \
                _Pragma("unroll")                                            \
                for (int ni = 0; ni < 8; ++ni)                               \
                    MMA16816(acc[mi][ni], af[cb][mi], wf[cb][ni]);           \
        }                                                                    \
    }

__global__ __launch_bounds__(128, 2) void gemm_qkv(
    const float* __restrict__ bq, const float* __restrict__ bk,
    const float* __restrict__ bv)
{
    extern __shared__ __align__(128) char dynsm[];
    __shared__ float bias_s[128];

    const int tid  = threadIdx.x;
    const int wid  = tid >> 5;
    const int lane = tid & 31;
    const int m0 = blockIdx.y << 7;
    const int n0 = blockIdx.x << 7;
    const int z  = blockIdx.z;
    const int wm = (wid >> 1) << 6;     // 0 or 64
    const int wn = (wid & 1) << 6;      // 0 or 64
    const int lr = lane & 15;
    const int lxh = (lane >> 4) << 4;

    const __half* A = (z == 0) ? g_aq  : (z == 1) ? g_ak  : g_av;
    const __half* W = (z == 0) ? g_wq1 : (z == 1) ? g_wk1 : g_wv1;
    const float* bias = (z == 0) ? bq : (z == 1) ? bk : bv;

    bias_s[tid] = bias[n0 + tid];

    const uint32_t sb0 = smem_u32(dynsm);
    const __half* pA = A + (size_t)m0 * 1024;
    const __half* pW = W + (size_t)n0 * 1024;

    float acc[4][8][4] = {};
    GEMM_BODY(pA, pW)

    // epilogue: scatter [B,H,S,dk]; z=0 Q (pre-scaled 0.125*log2e), z=1 K, z=2 V
    const int rbase = m0 + wm + (lane >> 2);
    const int cbase = n0 + wn + ((lane & 3) << 1);
    #pragma unroll
    for (int mi = 0; mi < 4; ++mi) {
        #pragma unroll
        for (int ni = 0; ni < 8; ++ni) {
            int col = cbase + (ni << 3);
            float b0 = bias_s[col - n0], b1 = bias_s[col - n0 + 1];
            #pragma unroll
            for (int half = 0; half < 2; ++half) {
                int row = rbase + (mi << 4) + (half << 3);
                float v0 = acc[mi][ni][half*2]   + b0;
                float v1 = acc[mi][ni][half*2+1] + b1;
                int h = col >> 6, d = col & 63;
                int bb = row >> 11, s = row & 2047;
                size_t idx = ((size_t)((bb << 4) + h) * 2048 + s) * 64 + d;
                if (z == 0) {
                    v0 *= 0.18033688f; v1 *= 0.18033688f;   // 0.125 * log2(e)
                    *reinterpret_cast<uint32_t*>(&g_q1[idx]) = pack_h2(v0, v1);
                } else if (z == 1) {
                    *reinterpret_cast<uint32_t*>(&g_k1[idx]) = pack_h2(v0, v1);
                } else {
                    *reinterpret_cast<uint32_t*>(&g_v1[idx]) = pack_h2(v0, v1);
                }
            }
        }
    }
}

__global__ __launch_bounds__(128, 2) void gemm_out(
    const float* __restrict__ bo, float* __restrict__ outf)
{
    extern __shared__ __align__(128) char dynsm[];
    __shared__ float bias_s[128];

    const int tid  = threadIdx.x;
    const int wid  = tid >> 5;
    const int lane = tid & 31;
    const int m0 = blockIdx.y << 7;
    const int n0 = blockIdx.x << 7;
    const int wm = (wid >> 1) << 6;
    const int wn = (wid & 1) << 6;
    const int lr = lane & 15;
    const int lxh = (lane >> 4) << 4;

    bias_s[tid] = bo[n0 + tid];

    const uint32_t sb0 = smem_u32(dynsm);
    const __half* pA = g_ao1 + (size_t)m0 * 1024;
    const __half* pW = g_wo1 + (size_t)n0 * 1024;

    float acc[4][8][4] = {};
    GEMM_BODY(pA, pW)

    const int rbase = m0 + wm + (lane >> 2);
    const int cbase = n0 + wn + ((lane & 3) << 1);
    #pragma unroll
    for (int mi = 0; mi < 4; ++mi)
        #pragma unroll
        for (int ni = 0; ni < 8; ++ni) {
            int col = cbase + (ni << 3);
            float b0 = bias_s[col - n0], b1 = bias_s[col - n0 + 1];
            #pragma unroll
            for (int half = 0; half < 2; ++half) {
                int row = rbase + (mi << 4) + (half << 3);
                *reinterpret_cast<float2*>(&outf[(size_t)row * 1024 + col]) =
                    make_float2(acc[mi][ni][half*2] + b0,
                                acc[mi][ni][half*2+1] + b1);
            }
        }
}

// ---------------- tensor-core flash attention --------------------------------
// CTA = 64 q-rows, 128 threads, 3 CTAs/SM (register diet), 2-stage pipeline,
// 2q x 2k warp split. S computed in two 32-k-col chunks (sc peak 32 regs);
// P consumed per chunk (ones-MMA row sums + PV). Math identical to R14.
#define ATT_KV 16384
#define ATT_MB 1024
#define ATT_STAGE (2*ATT_KV + ATT_MB)            // K, V, maskbits = 33792
#define ATT_SMEM (2*ATT_STAGE)                   // 67584 -> 3 CTAs = 202752

__device__ __forceinline__ void att_stage(
    uint32_t sb, const __half* __restrict__ K, const __half* __restrict__ V,
    const uint32_t* __restrict__ Mb, int kt, int q0, int tid)
{
    #pragma unroll
    for (int i = 0; i < 8; ++i) {
        int seg = tid + (i << 7);
        int row = seg >> 3, cs = seg & 7;
        uint32_t so = row * 128 + ((cs << 4) ^ ((row & 7) << 4));
        size_t gofs = (size_t)((kt << 7) + row) * 64 + (cs << 3);
        cpa16(sb + so,          K + gofs);
        cpa16(sb + ATT_KV + so, V + gofs);
    }
    if (tid < 64)
        cpa16(sb + 2*ATT_KV + tid * 16,
              (const char*)(Mb + (size_t)(q0 + tid) * 64) + (kt << 4));
    CP_COMMIT();
}

__global__ __launch_bounds__(128, 3) void attn_tc()
{
    extern __shared__ __align__(128) char sm[];
    const int tid  = threadIdx.x;
    const int wid  = tid >> 5;
    const int lane = tid & 31;
    const int bh = blockIdx.y;
    const int b = bh >> 4, h = bh & 15;
    const int q0 = blockIdx.x << 6;

    const uint32_t smb = smem_u32(sm);

    const size_t hofs = (size_t)bh * 2048 * 64;
    const __half* gq  = g_q1 + hofs + (size_t)q0 * 64;
    const __half* gk  = g_k1 + hofs;
    const __half* gv  = g_v1 + hofs;
    const uint32_t* gmb = g_mbits + (size_t)b * 2048 * 64;

    // ---- stage Q (single) through buffer 0, extract frags to registers ----
    #pragma unroll
    for (int i = 0; i < 4; ++i) {
        int seg = tid + (i << 7);
        int row = seg >> 3, cs = seg & 7;
        uint32_t so = row * 128 + ((cs << 4) ^ ((row & 7) << 4));
        cpa16(smb + so, gq + (size_t)row * 64 + (cs << 3));
    }
    CP_COMMIT();
    CP_WAIT(0);
    __syncthreads();

    const int lr  = lane & 15;
    const int lxh = (lane >> 4) << 4;
    const int r   = lane >> 2;
    const int c2  = (lane & 3) << 1;
    const int qh_i = wid & 1;          // q half: rows [qh_i*32, +32)
    const int kh   = wid >> 1;         // k half: cols [kh*64, +64) per tile

    uint32_t qf[2][4][4];
    #pragma unroll
    for (int m = 0; m < 2; ++m) {
        int row = (qh_i << 5) + (m << 4) + lr;
        uint32_t rb = smb + row * 128;
        uint32_t sw = (row & 7) << 4;
        #pragma unroll
        for (int kk = 0; kk < 4; ++kk) {
            uint32_t ad = rb + (((kk << 5) + lxh) ^ sw);
            LDSM4(qf[m][kk][0], qf[m][kk][1], qf[m][kk][2], qf[m][kk][3], ad);
        }
    }
    __syncthreads();   // all warps done reading Q before stage 0 overwrite

    att_stage(smb,             gk, gv, gmb, 0, q0, tid);
    att_stage(smb + ATT_STAGE, gk, gv, gmb, 1, q0, tid);

    float o[2][8][4] = {};
    float lacc[2][4] = {};
    const uint32_t ones[2] = {0x3C003C00u, 0x3C003C00u};

    for (int kt = 0; kt < 16; ++kt) {
        if (kt < 15) { CP_WAIT(1); } else { CP_WAIT(0); }
        __syncthreads();
        const uint32_t sb = smb + (kt & 1) * ATT_STAGE;
        const char* stp = sm + (kt & 1) * ATT_STAGE;

        // ---- two 32-k-col chunks within this warp's 64 cols ----
        #pragma unroll
        for (int ch = 0; ch < 2; ++ch) {
            // S = Q x K for chunk (32q x 32k per m-tile pair)
            float sc[2][4][4] = {};
            #pragma unroll
            for (int hg = 0; hg < 2; ++hg) {
                int krow = (kh << 6) + (ch << 5) + (hg << 4) + lr;
                uint32_t rb = sb + krow * 128;
                uint32_t sw = (krow & 7) << 4;
                #pragma unroll
                for (int kk = 0; kk < 4; ++kk) {
                    uint32_t ad = rb + (((kk << 5) + lxh) ^ sw);
                    uint32_t k0r, k1r, k2r, k3r;
                    LDSM4(k0r, k1r, k2r, k3r, ad);
                    uint32_t bE[2] = {k0r, k2r}, bO[2] = {k1r, k3r};
                    #pragma unroll
                    for (int m = 0; m < 2; ++m) {
                        MMA16816(sc[m][2*hg],   qf[m][kk], bE);
                        MMA16816(sc[m][2*hg+1], qf[m][kk], bO);
                    }
                }
            }

            // mask -> 0 (exp2(0)=1), pack, ex2.f16x2 -> P fragment
            uint32_t P[2][8];
            #pragma unroll
            for (int m = 0; m < 2; ++m) {
                int qr = (qh_i << 5) + (m << 4) + r;
                uint32_t w0 = *reinterpret_cast<const uint32_t*>(
                    stp + 2*ATT_KV + qr * 16 + (((kh << 1) + ch) << 2));
                uint32_t w1 = *reinterpret_cast<const uint32_t*>(
                    stp + 2*ATT_KV + (qr + 8) * 16 + (((kh << 1) + ch) << 2));
                #pragma unroll
                for (int nt = 0; nt < 4; ++nt) {
                    int sh = (nt << 3) + c2;
                    float s0 = ((w0 >> sh) & 1u)       ? sc[m][nt][0] : 0.0f;
                    float s1 = ((w0 >> (sh + 1)) & 1u) ? sc[m][nt][1] : 0.0f;
                    float s2 = ((w1 >> sh) & 1u)       ? sc[m][nt][2] : 0.0f;
                    float s3 = ((w1 >> (sh + 1)) & 1u) ? sc[m][nt][3] : 0.0f;
                    P[m][(nt << 1)]     = ex2_h2(pack_h2(s0, s1));
                    P[m][(nt << 1) + 1] = ex2_h2(pack_h2(s2, s3));
                }
            }

            // l partials on the tensor pipe
            #pragma unroll
            for (int m = 0; m < 2; ++m) {
                MMA16816(lacc[m], &P[m][0], ones);
                MMA16816(lacc[m], &P[m][4], ones);
            }

            // O partials += P x V (chunk's 32 k-rows)
            #pragma unroll
            for (int t = 0; t < 2; ++t) {
                int vrow = (kh << 6) + (ch << 5) + (t << 4) + lr;
                uint32_t rb = sb + ATT_KV + vrow * 128;
                uint32_t sw = (vrow & 7) << 4;
                #pragma unroll
                for (int dp = 0; dp < 4; ++dp) {
                    uint32_t ad = rb + (((dp << 5) + lxh) ^ sw);
                    uint32_t h0, h1, h2, h3;
                    LDSM4T(h0, h1, h2, h3, ad);
                    uint32_t bh0[2] = {h0, h1}, bh1[2] = {h2, h3};
                    #pragma unroll
                    for (int m = 0; m < 2; ++m) {
                        MMA16816(o[m][2*dp],   &P[m][t << 2], bh0);
                        MMA16816(o[m][2*dp+1], &P[m][t << 2], bh1);
                    }
                }
            }
        }

        __syncthreads();
        if (kt + 2 < 16)
            att_stage(smb + (kt & 1) * ATT_STAGE, gk, gv, gmb, kt + 2, q0, tid);
    }

    // ---- cross-warp reduction of O/l partials (k-halves), then store ----
    __syncthreads();               // all stage reads done; reuse smem
    float* Opart = reinterpret_cast<float*>(sm);           // 64q x 64d fp32
    float* Lpart = reinterpret_cast<float*>(sm + 16384);   // 64 floats

    if (kh == 1) {
        #pragma unroll
        for (int m = 0; m < 2; ++m) {
            int qrow = (qh_i << 5) + (m << 4) + r;
            #pragma unroll
            for (int ni = 0; ni < 8; ++ni) {
                int d = (ni << 3) + c2;
                Opart[qrow * 64 + d]       = o[m][ni][0];
                Opart[qrow * 64 + d + 1]   = o[m][ni][1];
                Opart[(qrow + 8) * 64 + d]     = o[m][ni][2];
                Opart[(qrow + 8) * 64 + d + 1] = o[m][ni][3];
            }
            Lpart[qrow]     = lacc[m][0];
            Lpart[qrow + 8] = lacc[m][2];
        }
    }
    __syncthreads();
    if (kh == 0) {
        #pragma unroll
        for (int m = 0; m < 2; ++m) {
            int qrow = (qh_i << 5) + (m << 4) + r;
            float i0 = 1.f / (lacc[m][0] + Lpart[qrow]);
            float i1 = 1.f / (lacc[m][2] + Lpart[qrow + 8]);
            int grow = q0 + qrow;
            size_t base0 = ((size_t)(b * 2048) + grow) * 1024 + h * 64;
            size_t base1 = base0 + 8 * 1024;
            #pragma unroll
            for (int ni = 0; ni < 8; ++ni) {
                int d = (ni << 3) + c2;
                float v0 = (o[m][ni][0] + Opart[qrow * 64 + d])       * i0;
                float v1 = (o[m][ni][1] + Opart[qrow * 64 + d + 1])   * i0;
                float v2 = (o[m][ni][2] + Opart[(qrow + 8) * 64 + d])     * i1;
                float v3 = (o[m][ni][3] + Opart[(qrow + 8) * 64 + d + 1]) * i1;
                *reinterpret_cast<uint32_t*>(&g_ao1[base0 + d]) = pack_h2(v0, v1);
                *reinterpret_cast<uint32_t*>(&g_ao1[base1 + d]) = pack_h2(v2, v3);
            }
        }
    }
}

// ---------------------------------------------------------------------------
extern "C" void kernel_launch(void* const* d_in, const int* in_sizes, int n_in,
                              void* d_out, int out_size)
{
    const float* query = (const float*)d_in[0];
    const float* key_  = (const float*)d_in[1];
    const float* value = (const float*)d_in[2];
    const int*   mask  = (const int*)  d_in[3];
    const float* wq = (const float*)d_in[4];
    const float* bq = (const float*)d_in[5];
    const float* wk = (const float*)d_in[6];
    const float* bk = (const float*)d_in[7];
    const float* wv = (const float*)d_in[8];
    const float* bv = (const float*)d_in[9];
    const float* wo = (const float*)d_in[10];
    const float* bo = (const float*)d_in[11];

    void *paq, *pak, *pav, *pwq, *pwk, *pwv, *pwo, *pmb;
    cudaGetSymbolAddress(&paq, g_aq);
    cudaGetSymbolAddress(&pak, g_ak);
    cudaGetSymbolAddress(&pav, g_av);
    cudaGetSymbolAddress(&pwq, g_wq1);
    cudaGetSymbolAddress(&pwk, g_wk1);
    cudaGetSymbolAddress(&pwv, g_wv1);
    cudaGetSymbolAddress(&pwo, g_wo1);
    cudaGetSymbolAddress(&pmb, g_mbits);

    cudaFuncSetAttribute(gemm_qkv,
                         cudaFuncAttributeMaxDynamicSharedMemorySize, G_SMEM);
    cudaFuncSetAttribute(gemm_out,
                         cudaFuncAttributeMaxDynamicSharedMemorySize, G_SMEM);
    cudaFuncSetAttribute(attn_tc,
                         cudaFuncAttributeMaxDynamicSharedMemorySize, ATT_SMEM);

    conv_maskbits<<<16384, 256>>>((const int4*)mask, (uint32_t*)pmb);
    conv_h1x3<<<dim3(2048, 3), 256>>>(
        (const float4*)query, (const float4*)key_, (const float4*)value,
        (uint2*)paq, (uint2*)pak, (uint2*)pav);
    conv_h1x4<<<dim3(256, 4), 256>>>(
        (const float4*)wq, (const float4*)wk, (const float4*)wv,
        (const float4*)wo,
        (uint2*)pwq, (uint2*)pwk, (uint2*)pwv, (uint2*)pwo);

    gemm_qkv<<<dim3(8, 64, 3), 128, G_SMEM>>>(bq, bk, bv);
    attn_tc<<<dim3(32, 64), 128, ATT_SMEM>>>();
    gemm_out<<<dim3(8, 64), 128, G_SMEM>>>(bo, (float*)d_out);
}

// round 16
// speedup vs baseline: 1.5009x; 1.0122x over previous
#include <cuda_runtime.h>
#include <cuda_fp16.h>
#include <cstdint>

// ---------------- scratch (__device__ globals; no allocs allowed) -----------
__device__ __half g_aq[8192*1024];             // fp16 A inputs (single)
__device__ __half g_ak[8192*1024];
__device__ __half g_av[8192*1024];
__device__ __half g_ao1[8192*1024];            // attention out (single fp16)
__device__ __half g_wq1[1024*1024];            // weights single fp16
__device__ __half g_wk1[1024*1024];
__device__ __half g_wv1[1024*1024];
__device__ __half g_wo1[1024*1024];
__device__ __half g_q1 [4*16*2048*64];         // Q single (pre-scaled 0.125*log2e)
__device__ __half g_k1 [4*16*2048*64];         // K single
__device__ __half g_v1 [4*16*2048*64];         // V single
__device__ uint32_t g_mbits[4*2048*64];        // bit mask: 64 words per row

// ---------------- PTX helpers (generic ISA, valid at compute_103) -----------
__device__ __forceinline__ uint32_t smem_u32(const void* p) {
    uint32_t a;
    asm("{ .reg .u64 t; cvta.to.shared.u64 t, %1; cvt.u32.u64 %0, t; }"
        : "=r"(a) : "l"(p));
    return a;
}
__device__ __forceinline__ void cpa16(uint32_t dst, const void* src) {
    asm volatile("cp.async.cg.shared.global [%0], [%1], 16;"
                 :: "r"(dst), "l"(src) : "memory");
}
#define CP_COMMIT() asm volatile("cp.async.commit_group;" ::: "memory")
#define CP_WAIT(n)  asm volatile("cp.async.wait_group %0;" :: "n"(n) : "memory")

#define LDSM4(r0, r1, r2, r3, addr)                                          \
    asm volatile("ldmatrix.sync.aligned.m8n8.x4.shared.b16 {%0,%1,%2,%3}, [%4];" \
                 : "=r"(r0), "=r"(r1), "=r"(r2), "=r"(r3) : "r"(addr))
#define LDSM4T(r0, r1, r2, r3, addr)                                         \
    asm volatile("ldmatrix.sync.aligned.m8n8.x4.trans.shared.b16 {%0,%1,%2,%3}, [%4];" \
                 : "=r"(r0), "=r"(r1), "=r"(r2), "=r"(r3) : "r"(addr))

#define MMA16816(d, a, b)                                                    \
    asm volatile("mma.sync.aligned.m16n8k16.row.col.f32.f16.f16.f32 "        \
                 "{%0,%1,%2,%3}, {%4,%5,%6,%7}, {%8,%9}, {%0,%1,%2,%3};"     \
                 : "+f"((d)[0]), "+f"((d)[1]), "+f"((d)[2]), "+f"((d)[3])    \
                 : "r"((a)[0]), "r"((a)[1]), "r"((a)[2]), "r"((a)[3]),       \
                   "r"((b)[0]), "r"((b)[1]))

__device__ __forceinline__ uint32_t pack_h2(float a, float b) {
    __half2 h = __floats2half2_rn(a, b);
    return *reinterpret_cast<uint32_t*>(&h);
}
__device__ __forceinline__ uint32_t ex2_h2(uint32_t h2) {
    uint32_t r;
    asm("ex2.approx.f16x2 %0, %1;" : "=r"(r) : "r"(h2));
    return r;
}

// ---------------- conversions (fused launches, 4x ILP) -----------------------
__global__ __launch_bounds__(256) void conv_h1x3(
    const float4* __restrict__ s0, const float4* __restrict__ s1,
    const float4* __restrict__ s2, uint2* __restrict__ d0,
    uint2* __restrict__ d1, uint2* __restrict__ d2)
{
    int z = blockIdx.y;
    const float4* src = (z == 0) ? s0 : (z == 1) ? s1 : s2;
    uint2* dst = (z == 0) ? d0 : (z == 1) ? d1 : d2;
    int i = (blockIdx.x * blockDim.x + threadIdx.x) << 2;
    float4 v0 = src[i], v1 = src[i+1], v2 = src[i+2], v3 = src[i+3];
    dst[i]   = make_uint2(pack_h2(v0.x, v0.y), pack_h2(v0.z, v0.w));
    dst[i+1] = make_uint2(pack_h2(v1.x, v1.y), pack_h2(v1.z, v1.w));
    dst[i+2] = make_uint2(pack_h2(v2.x, v2.y), pack_h2(v2.z, v2.w));
    dst[i+3] = make_uint2(pack_h2(v3.x, v3.y), pack_h2(v3.z, v3.w));
}

__global__ __launch_bounds__(256) void conv_h1x4(
    const float4* __restrict__ s0, const float4* __restrict__ s1,
    const float4* __restrict__ s2, const float4* __restrict__ s3,
    uint2* __restrict__ d0, uint2* __restrict__ d1,
    uint2* __restrict__ d2, uint2* __restrict__ d3)
{
    int z = blockIdx.y;
    const float4* src = (z == 0) ? s0 : (z == 1) ? s1 : (z == 2) ? s2 : s3;
    uint2* dst = (z == 0) ? d0 : (z == 1) ? d1 : (z == 2) ? d2 : d3;
    int i = (blockIdx.x * blockDim.x + threadIdx.x) << 2;
    float4 v0 = src[i], v1 = src[i+1], v2 = src[i+2], v3 = src[i+3];
    dst[i]   = make_uint2(pack_h2(v0.x, v0.y), pack_h2(v0.z, v0.w));
    dst[i+1] = make_uint2(pack_h2(v1.x, v1.y), pack_h2(v1.z, v1.w));
    dst[i+2] = make_uint2(pack_h2(v2.x, v2.y), pack_h2(v2.z, v2.w));
    dst[i+3] = make_uint2(pack_h2(v3.x, v3.y), pack_h2(v3.z, v3.w));
}

__global__ __launch_bounds__(256) void conv_maskbits(
    const int4* __restrict__ src4, uint32_t* __restrict__ dst)
{
    int warp = (blockIdx.x * blockDim.x + threadIdx.x) >> 5;
    int lane = threadIdx.x & 31;
    int4 v = src4[(size_t)warp * 32 + lane];
    uint32_t nib = (v.x != 0 ? 1u : 0u) | (v.y != 0 ? 2u : 0u) |
                   (v.z != 0 ? 4u : 0u) | (v.w != 0 ? 8u : 0u);
    uint32_t word = nib << ((lane & 7) << 2);
    word |= __shfl_xor_sync(~0u, word, 1);
    word |= __shfl_xor_sync(~0u, word, 2);
    word |= __shfl_xor_sync(~0u, word, 4);
    if ((lane & 7) == 0) dst[(size_t)warp * 4 + (lane >> 3)] = word;
}

// ---------------- fp16 single-term GEMM core (mma.sync) ---------------------
// C = A(fp16) @ W(fp16)^T. CTA 128x128, BK=64, 3-stage cp.async, 2 CTAs/SM.
#define G_MAT 16384
#define G_STAGE (2 * G_MAT)                  // A, W = 32768
#define G_SMEM (3 * G_STAGE)                 // 98304

__device__ __forceinline__ void g_stage2(
    uint32_t sb, const __half* __restrict__ pA, const __half* __restrict__ pW,
    int kt, int tid)
{
    const __half* srcs[2] = {pA, pW};
    #pragma unroll
    for (int m = 0; m < 2; ++m) {
        uint32_t mb = sb + m * G_MAT;
        const __half* sp = srcs[m];
        #pragma unroll
        for (int i = 0; i < 8; ++i) {
            int seg = tid + (i << 7);
            int row = seg >> 3, cs = seg & 7;
            cpa16(mb + row * 128 + ((cs << 4) ^ ((row & 7) << 4)),
                  sp + (size_t)row * 1024 + (kt << 6) + (cs << 3));
        }
    }
    CP_COMMIT();
}

#define GLOAD(buf, kk, sb)                                                   \
    do {                                                                     \
        const int x_ = ((kk) << 5) + lxh;                                    \
        _Pragma("unroll")                                                    \
        for (int mi = 0; mi < 4; ++mi) {                                     \
            int row = wm + (mi << 4) + lr;                                   \
            uint32_t ad = (sb) + row * 128 + (x_ ^ ((row & 7) << 4));        \
            LDSM4(af[buf][mi][0], af[buf][mi][1], af[buf][mi][2],            \
                  af[buf][mi][3], ad);                                       \
        }                                                                    \
        _Pragma("unroll")                                                    \
        for (int g = 0; g < 4; ++g) {                                        \
            int row = wn + (g << 4) + lr;                                    \
            uint32_t wd = (sb) + G_MAT + row * 128 + (x_ ^ ((row & 7) << 4));\
            uint32_t r0, r1, r2, r3;                                         \
            LDSM4(r0, r1, r2, r3, wd);                                       \
            wf[buf][2*g][0] = r0; wf[buf][2*g][1] = r2;                      \
            wf[buf][2*g+1][0] = r1; wf[buf][2*g+1][1] = r3;                  \
        }                                                                    \
    } while (0)

#define GEMM_BODY(pA, pW)                                                    \
    g_stage2(sb0,           (pA), (pW), 0, tid);                             \
    g_stage2(sb0 + G_STAGE, (pA), (pW), 1, tid);                             \
    uint32_t af[2][4][4], wf[2][8][2];                                       \
    for (int j = 0; j < 16; ++j) {                                           \
        if (j < 15) { CP_WAIT(1); } else { CP_WAIT(0); }                     \
        __syncthreads();                                                     \
        if (j + 2 < 16)                                                      \
            g_stage2(sb0 + ((j + 2) % 3) * G_STAGE, (pA), (pW), j + 2, tid); \
        const uint32_t sb = sb0 + (j % 3) * G_STAGE;                         \
        GLOAD(0, 0, sb);                                                     \
        _Pragma("unroll")                                                    \
        for (int kk = 0; kk < 4; ++kk) {                                     \
            if (kk < 3) GLOAD((kk + 1) & 1, kk + 1, sb);                     \
            const int cb = kk & 1;                                           \
            _Pragma("unroll")                                                \
            for (int mi = 0; mi < 4; ++mi)                                   \
                _Pragma("unroll")                                            \
                for (int ni = 0; ni < 8; ++ni)                               \
                    MMA16816(acc[mi][ni], af[cb][mi], wf[cb][ni]);           \
        }                                                                    \
    }

__global__ __launch_bounds__(128, 2) void gemm_qkv(
    const float* __restrict__ bq, const float* __restrict__ bk,
    const float* __restrict__ bv)
{
    extern __shared__ __align__(128) char dynsm[];
    __shared__ float bias_s[128];

    const int tid  = threadIdx.x;
    const int wid  = tid >> 5;
    const int lane = tid & 31;
    const int m0 = blockIdx.y << 7;
    const int n0 = blockIdx.x << 7;
    const int z  = blockIdx.z;
    const int wm = (wid >> 1) << 6;     // 0 or 64
    const int wn = (wid & 1) << 6;      // 0 or 64
    const int lr = lane & 15;
    const int lxh = (lane >> 4) << 4;

    const __half* A = (z == 0) ? g_aq  : (z == 1) ? g_ak  : g_av;
    const __half* W = (z == 0) ? g_wq1 : (z == 1) ? g_wk1 : g_wv1;
    const float* bias = (z == 0) ? bq : (z == 1) ? bk : bv;

    bias_s[tid] = bias[n0 + tid];

    const uint32_t sb0 = smem_u32(dynsm);
    const __half* pA = A + (size_t)m0 * 1024;
    const __half* pW = W + (size_t)n0 * 1024;

    float acc[4][8][4] = {};
    GEMM_BODY(pA, pW)

    // epilogue: scatter [B,H,S,dk]; z=0 Q (pre-scaled 0.125*log2e), z=1 K, z=2 V
    const int rbase = m0 + wm + (lane >> 2);
    const int cbase = n0 + wn + ((lane & 3) << 1);
    #pragma unroll
    for (int mi = 0; mi < 4; ++mi) {
        #pragma unroll
        for (int ni = 0; ni < 8; ++ni) {
            int col = cbase + (ni << 3);
            float b0 = bias_s[col - n0], b1 = bias_s[col - n0 + 1];
            #pragma unroll
            for (int half = 0; half < 2; ++half) {
                int row = rbase + (mi << 4) + (half << 3);
                float v0 = acc[mi][ni][half*2]   + b0;
                float v1 = acc[mi][ni][half*2+1] + b1;
                int h = col >> 6, d = col & 63;
                int bb = row >> 11, s = row & 2047;
                size_t idx = ((size_t)((bb << 4) + h) * 2048 + s) * 64 + d;
                if (z == 0) {
                    v0 *= 0.18033688f; v1 *= 0.18033688f;   // 0.125 * log2(e)
                    *reinterpret_cast<uint32_t*>(&g_q1[idx]) = pack_h2(v0, v1);
                } else if (z == 1) {
                    *reinterpret_cast<uint32_t*>(&g_k1[idx]) = pack_h2(v0, v1);
                } else {
                    *reinterpret_cast<uint32_t*>(&g_v1[idx]) = pack_h2(v0, v1);
                }
            }
        }
    }
}

__global__ __launch_bounds__(128, 2) void gemm_out(
    const float* __restrict__ bo, float* __restrict__ outf)
{
    extern __shared__ __align__(128) char dynsm[];
    __shared__ float bias_s[128];

    const int tid  = threadIdx.x;
    const int wid  = tid >> 5;
    const int lane = tid & 31;
    const int m0 = blockIdx.y << 7;
    const int n0 = blockIdx.x << 7;
    const int wm = (wid >> 1) << 6;
    const int wn = (wid & 1) << 6;
    const int lr = lane & 15;
    const int lxh = (lane >> 4) << 4;

    bias_s[tid] = bo[n0 + tid];

    const uint32_t sb0 = smem_u32(dynsm);
    const __half* pA = g_ao1 + (size_t)m0 * 1024;
    const __half* pW = g_wo1 + (size_t)n0 * 1024;

    float acc[4][8][4] = {};
    GEMM_BODY(pA, pW)

    const int rbase = m0 + wm + (lane >> 2);
    const int cbase = n0 + wn + ((lane & 3) << 1);
    #pragma unroll
    for (int mi = 0; mi < 4; ++mi)
        #pragma unroll
        for (int ni = 0; ni < 8; ++ni) {
            int col = cbase + (ni << 3);
            float b0 = bias_s[col - n0], b1 = bias_s[col - n0 + 1];
            #pragma unroll
            for (int half = 0; half < 2; ++half) {
                int row = rbase + (mi << 4) + (half << 3);
                *reinterpret_cast<float2*>(&outf[(size_t)row * 1024 + col]) =
                    make_float2(acc[mi][ni][half*2] + b0,
                                acc[mi][ni][half*2+1] + b1);
            }
        }
}

// ---------------- tensor-core flash attention --------------------------------
// CTA = 64 q-rows, 128 threads, 2 CTAs/SM, 3-STAGE ring with ONE barrier per
// kv-iter (stage written at kt is (kt+2)%3, which last had readers at kt-1;
// the top barrier of kt already fences those). 2q x 2k warp split; S in two
// 32-col chunks; mask->0 + ex2.f16x2 softmax; l via ones-MMA. Math == R14/15.
#define ATT_KV 16384
#define ATT_MB 1024
#define ATT_STAGE (2*ATT_KV + ATT_MB)            // K, V, maskbits = 33792
#define ATT_SMEM (3*ATT_STAGE)                   // 101376 -> 2 CTAs/SM

__device__ __forceinline__ void att_stage(
    uint32_t sb, const __half* __restrict__ K, const __half* __restrict__ V,
    const uint32_t* __restrict__ Mb, int kt, int q0, int tid)
{
    #pragma unroll
    for (int i = 0; i < 8; ++i) {
        int seg = tid + (i << 7);
        int row = seg >> 3, cs = seg & 7;
        uint32_t so = row * 128 + ((cs << 4) ^ ((row & 7) << 4));
        size_t gofs = (size_t)((kt << 7) + row) * 64 + (cs << 3);
        cpa16(sb + so,          K + gofs);
        cpa16(sb + ATT_KV + so, V + gofs);
    }
    if (tid < 64)
        cpa16(sb + 2*ATT_KV + tid * 16,
              (const char*)(Mb + (size_t)(q0 + tid) * 64) + (kt << 4));
    CP_COMMIT();
}

__global__ __launch_bounds__(128, 2) void attn_tc()
{
    extern __shared__ __align__(128) char sm[];
    const int tid  = threadIdx.x;
    const int wid  = tid >> 5;
    const int lane = tid & 31;
    const int bh = blockIdx.y;
    const int b = bh >> 4, h = bh & 15;
    const int q0 = blockIdx.x << 6;

    const uint32_t smb = smem_u32(sm);

    const size_t hofs = (size_t)bh * 2048 * 64;
    const __half* gq  = g_q1 + hofs + (size_t)q0 * 64;
    const __half* gk  = g_k1 + hofs;
    const __half* gv  = g_v1 + hofs;
    const uint32_t* gmb = g_mbits + (size_t)b * 2048 * 64;

    // ---- stage Q (single) through buffer 0, extract frags to registers ----
    #pragma unroll
    for (int i = 0; i < 4; ++i) {
        int seg = tid + (i << 7);
        int row = seg >> 3, cs = seg & 7;
        uint32_t so = row * 128 + ((cs << 4) ^ ((row & 7) << 4));
        cpa16(smb + so, gq + (size_t)row * 64 + (cs << 3));
    }
    CP_COMMIT();
    CP_WAIT(0);
    __syncthreads();

    const int lr  = lane & 15;
    const int lxh = (lane >> 4) << 4;
    const int r   = lane >> 2;
    const int c2  = (lane & 3) << 1;
    const int qh_i = wid & 1;          // q half: rows [qh_i*32, +32)
    const int kh   = wid >> 1;         // k half: cols [kh*64, +64) per tile

    uint32_t qf[2][4][4];
    #pragma unroll
    for (int m = 0; m < 2; ++m) {
        int row = (qh_i << 5) + (m << 4) + lr;
        uint32_t rb = smb + row * 128;
        uint32_t sw = (row & 7) << 4;
        #pragma unroll
        for (int kk = 0; kk < 4; ++kk) {
            uint32_t ad = rb + (((kk << 5) + lxh) ^ sw);
            LDSM4(qf[m][kk][0], qf[m][kk][1], qf[m][kk][2], qf[m][kk][3], ad);
        }
    }
    __syncthreads();   // all warps done reading Q before stage 0 overwrite

    att_stage(smb,             gk, gv, gmb, 0, q0, tid);
    att_stage(smb + ATT_STAGE, gk, gv, gmb, 1, q0, tid);

    float o[2][8][4] = {};
    float lacc[2][4] = {};
    const uint32_t ones[2] = {0x3C003C00u, 0x3C003C00u};

    for (int kt = 0; kt < 16; ++kt) {
        if (kt < 15) { CP_WAIT(1); } else { CP_WAIT(0); }
        __syncthreads();                         // the ONLY barrier per iter
        if (kt + 2 < 16)
            att_stage(smb + ((kt + 2) % 3) * ATT_STAGE, gk, gv, gmb,
                      kt + 2, q0, tid);
        const uint32_t sb = smb + (kt % 3) * ATT_STAGE;
        const char* stp = sm + (kt % 3) * ATT_STAGE;

        // ---- two 32-k-col chunks within this warp's 64 cols ----
        #pragma unroll
        for (int ch = 0; ch < 2; ++ch) {
            // S = Q x K for chunk (32q x 32k per m-tile pair)
            float sc[2][4][4] = {};
            #pragma unroll
            for (int hg = 0; hg < 2; ++hg) {
                int krow = (kh << 6) + (ch << 5) + (hg << 4) + lr;
                uint32_t rb = sb + krow * 128;
                uint32_t sw = (krow & 7) << 4;
                #pragma unroll
                for (int kk = 0; kk < 4; ++kk) {
                    uint32_t ad = rb + (((kk << 5) + lxh) ^ sw);
                    uint32_t k0r, k1r, k2r, k3r;
                    LDSM4(k0r, k1r, k2r, k3r, ad);
                    uint32_t bE[2] = {k0r, k2r}, bO[2] = {k1r, k3r};
                    #pragma unroll
                    for (int m = 0; m < 2; ++m) {
                        MMA16816(sc[m][2*hg],   qf[m][kk], bE);
                        MMA16816(sc[m][2*hg+1], qf[m][kk], bO);
                    }
                }
            }

            // mask -> 0 (exp2(0)=1), pack, ex2.f16x2 -> P fragment
            uint32_t P[2][8];
            #pragma unroll
            for (int m = 0; m < 2; ++m) {
                int qr = (qh_i << 5) + (m << 4) + r;
                uint32_t w0 = *reinterpret_cast<const uint32_t*>(
                    stp + 2*ATT_KV + qr * 16 + (((kh << 1) + ch) << 2));
                uint32_t w1 = *reinterpret_cast<const uint32_t*>(
                    stp + 2*ATT_KV + (qr + 8) * 16 + (((kh << 1) + ch) << 2));
                #pragma unroll
                for (int nt = 0; nt < 4; ++nt) {
                    int sh = (nt << 3) + c2;
                    float s0 = ((w0 >> sh) & 1u)       ? sc[m][nt][0] : 0.0f;
                    float s1 = ((w0 >> (sh + 1)) & 1u) ? sc[m][nt][1] : 0.0f;
                    float s2 = ((w1 >> sh) & 1u)       ? sc[m][nt][2] : 0.0f;
                    float s3 = ((w1 >> (sh + 1)) & 1u) ? sc[m][nt][3] : 0.0f;
                    P[m][(nt << 1)]     = ex2_h2(pack_h2(s0, s1));
                    P[m][(nt << 1) + 1] = ex2_h2(pack_h2(s2, s3));
                }
            }

            // l partials on the tensor pipe
            #pragma unroll
            for (int m = 0; m < 2; ++m) {
                MMA16816(lacc[m], &P[m][0], ones);
                MMA16816(lacc[m], &P[m][4], ones);
            }

            // O partials += P x V (chunk's 32 k-rows)
            #pragma unroll
            for (int t = 0; t < 2; ++t) {
                int vrow = (kh << 6) + (ch << 5) + (t << 4) + lr;
                uint32_t rb = sb + ATT_KV + vrow * 128;
                uint32_t sw = (vrow & 7) << 4;
                #pragma unroll
                for (int dp = 0; dp < 4; ++dp) {
                    uint32_t ad = rb + (((dp << 5) + lxh) ^ sw);
                    uint32_t h0, h1, h2, h3;
                    LDSM4T(h0, h1, h2, h3, ad);
                    uint32_t bh0[2] = {h0, h1}, bh1[2] = {h2, h3};
                    #pragma unroll
                    for (int m = 0; m < 2; ++m) {
                        MMA16816(o[m][2*dp],   &P[m][t << 2], bh0);
                        MMA16816(o[m][2*dp+1], &P[m][t << 2], bh1);
                    }
                }
            }
        }
        // no bottom barrier: 3-stage ring makes restage target disjoint from
        // any buffer still being read within 1 iter of skew.
    }

    // ---- cross-warp reduction of O/l partials (k-halves), then store ----
    __syncthreads();               // all stage reads done; reuse smem
    float* Opart = reinterpret_cast<float*>(sm);           // 64q x 64d fp32
    float* Lpart = reinterpret_cast<float*>(sm + 16384);   // 64 floats

    if (kh == 1) {
        #pragma unroll
        for (int m = 0; m < 2; ++m) {
            int qrow = (qh_i << 5) + (m << 4) + r;
            #pragma unroll
            for (int ni = 0; ni < 8; ++ni) {
                int d = (ni << 3) + c2;
                Opart[qrow * 64 + d]       = o[m][ni][0];
                Opart[qrow * 64 + d + 1]   = o[m][ni][1];
                Opart[(qrow + 8) * 64 + d]     = o[m][ni][2];
                Opart[(qrow + 8) * 64 + d + 1] = o[m][ni][3];
            }
            Lpart[qrow]     = lacc[m][0];
            Lpart[qrow + 8] = lacc[m][2];
        }
    }
    __syncthreads();
    if (kh == 0) {
        #pragma unroll
        for (int m = 0; m < 2; ++m) {
            int qrow = (qh_i << 5) + (m << 4) + r;
            float i0 = 1.f / (lacc[m][0] + Lpart[qrow]);
            float i1 = 1.f / (lacc[m][2] + Lpart[qrow + 8]);
            int grow = q0 + qrow;
            size_t base0 = ((size_t)(b * 2048) + grow) * 1024 + h * 64;
            size_t base1 = base0 + 8 * 1024;
            #pragma unroll
            for (int ni = 0; ni < 8; ++ni) {
                int d = (ni << 3) + c2;
                float v0 = (o[m][ni][0] + Opart[qrow * 64 + d])       * i0;
                float v1 = (o[m][ni][1] + Opart[qrow * 64 + d + 1])   * i0;
                float v2 = (o[m][ni][2] + Opart[(qrow + 8) * 64 + d])     * i1;
                float v3 = (o[m][ni][3] + Opart[(qrow + 8) * 64 + d + 1]) * i1;
                *reinterpret_cast<uint32_t*>(&g_ao1[base0 + d]) = pack_h2(v0, v1);
                *reinterpret_cast<uint32_t*>(&g_ao1[base1 + d]) = pack_h2(v2, v3);
            }
        }
    }
}

// ---------------------------------------------------------------------------
extern "C" void kernel_launch(void* const* d_in, const int* in_sizes, int n_in,
                              void* d_out, int out_size)
{
    const float* query = (const float*)d_in[0];
    const float* key_  = (const float*)d_in[1];
    const float* value = (const float*)d_in[2];
    const int*   mask  = (const int*)  d_in[3];
    const float* wq = (const float*)d_in[4];
    const float* bq = (const float*)d_in[5];
    const float* wk = (const float*)d_in[6];
    const float* bk = (const float*)d_in[7];
    const float* wv = (const float*)d_in[8];
    const float* bv = (const float*)d_in[9];
    const float* wo = (const float*)d_in[10];
    const float* bo = (const float*)d_in[11];

    void *paq, *pak, *pav, *pwq, *pwk, *pwv, *pwo, *pmb;
    cudaGetSymbolAddress(&paq, g_aq);
    cudaGetSymbolAddress(&pak, g_ak);
    cudaGetSymbolAddress(&pav, g_av);
    cudaGetSymbolAddress(&pwq, g_wq1);
    cudaGetSymbolAddress(&pwk, g_wk1);
    cudaGetSymbolAddress(&pwv, g_wv1);
    cudaGetSymbolAddress(&pwo, g_wo1);
    cudaGetSymbolAddress(&pmb, g_mbits);

    cudaFuncSetAttribute(gemm_qkv,
                         cudaFuncAttributeMaxDynamicSharedMemorySize, G_SMEM);
    cudaFuncSetAttribute(gemm_out,
                         cudaFuncAttributeMaxDynamicSharedMemorySize, G_SMEM);
    cudaFuncSetAttribute(attn_tc,
                         cudaFuncAttributeMaxDynamicSharedMemorySize, ATT_SMEM);

    conv_maskbits<<<16384, 256>>>((const int4*)mask, (uint32_t*)pmb);
    conv_h1x3<<<dim3(2048, 3), 256>>>(
        (const float4*)query, (const float4*)key_, (const float4*)value,
        (uint2*)paq, (uint2*)pak, (uint2*)pav);
    conv_h1x4<<<dim3(256, 4), 256>>>(
        (const float4*)wq, (const float4*)wk, (const float4*)wv,
        (const float4*)wo,
        (uint2*)pwq, (uint2*)pwk, (uint2*)pwv, (uint2*)pwo);

    gemm_qkv<<<dim3(8, 64, 3), 128, G_SMEM>>>(bq, bk, bv);
    attn_tc<<<dim3(32, 64), 128, ATT_SMEM>>>();
    gemm_out<<<dim3(8, 64), 128, G_SMEM>>>(bo, (float*)d_out);
}